// round 9
// baseline (speedup 1.0000x reference)
#include <cuda_runtime.h>
#include <cuda_fp16.h>
#include <cstdint>
#include <cmath>

// ---------------- problem constants ----------------
#define T_TOK  8192
#define D_DIM  1024
#define E_EXP  8
#define H_DIM  4096
#define MPAD   17408
#define MTILES 136

#define XE   8388608L
#define WR1E 1048576L
#define W1E  33554432L
#define W2E  33554432L

// ---------------- scratch ----------------
__device__ float  g_H1[(size_t)T_TOK * D_DIM];   // router hidden (fp32)
__device__ __half g_h [(size_t)MPAD * H_DIM];    // expert hidden (fp16)
__device__ __half g_W1h[W1E];                    // fp16(W1) [E][D][H]
__device__ __half g_W2h[W2E];                    // fp16(W2) [E][H][D]
__device__ __half g_xh[XE];
__device__ __half g_xl[XE];
__device__ __half g_wh[WR1E];
__device__ __half g_wl[WR1E];
__device__ int    g_topk_idx[T_TOK * 2];
__device__ float  g_topk_w [T_TOK * 2];
__device__ float  g_wslot  [MPAD];               // per-slot combine weight
__device__ int    g_counts [E_EXP];
__device__ int    g_perm   [MPAD];
__device__ int    g_slot   [T_TOK * 2];
__device__ int    g_tile_expert[MTILES];
__device__ int    g_done;

// ---------------- helpers ----------------
__device__ __forceinline__ float gelu_exact(float x) {
    return 0.5f * x * (1.0f + erff(x * 0.70710678118654752440f));
}
__device__ __forceinline__ void mma_f16(float c[4],
                                        uint32_t a0, uint32_t a1, uint32_t a2, uint32_t a3,
                                        uint32_t b0, uint32_t b1) {
    asm volatile(
        "mma.sync.aligned.m16n8k16.row.col.f32.f16.f16.f32 "
        "{%0,%1,%2,%3}, {%4,%5,%6,%7}, {%8,%9}, {%0,%1,%2,%3};\n"
        : "+f"(c[0]), "+f"(c[1]), "+f"(c[2]), "+f"(c[3])
        : "r"(a0), "r"(a1), "r"(a2), "r"(a3), "r"(b0), "r"(b1));
}
__device__ __forceinline__ void ldsm_x4(uint32_t& r0, uint32_t& r1, uint32_t& r2, uint32_t& r3,
                                        uint32_t addr) {
    asm volatile("ldmatrix.sync.aligned.m8n8.x4.shared.b16 {%0,%1,%2,%3}, [%4];"
                 : "=r"(r0), "=r"(r1), "=r"(r2), "=r"(r3) : "r"(addr));
}
__device__ __forceinline__ void ldsm_x4_t(uint32_t& r0, uint32_t& r1, uint32_t& r2, uint32_t& r3,
                                          uint32_t addr) {
    asm volatile("ldmatrix.sync.aligned.m8n8.x4.trans.shared.b16 {%0,%1,%2,%3}, [%4];"
                 : "=r"(r0), "=r"(r1), "=r"(r2), "=r"(r3) : "r"(addr));
}
__device__ __forceinline__ void cp_async16(void* smem_dst, const void* gmem_src, unsigned src_bytes) {
    unsigned d = (unsigned)__cvta_generic_to_shared(smem_dst);
    asm volatile("cp.async.ca.shared.global [%0], [%1], 16, %2;\n"
                 :: "r"(d), "l"(gmem_src), "r"(src_bytes) : "memory");
}
__device__ __forceinline__ void cp_async16_ca(uint32_t smem_dst, const void* gmem_src) {
    asm volatile("cp.async.ca.shared.global [%0], [%1], 16;\n"
                 :: "r"(smem_dst), "l"(gmem_src) : "memory");
}
__device__ __forceinline__ void cp_async16_cg(uint32_t smem_dst, const void* gmem_src) {
    asm volatile("cp.async.cg.shared.global [%0], [%1], 16;\n"
                 :: "r"(smem_dst), "l"(gmem_src) : "memory");
}
__device__ __forceinline__ uint32_t smem_u32(const void* p) {
    return (uint32_t)__cvta_generic_to_shared(p);
}

// ---------------- main GEMM tiling (BK=32, 4-stage, frag double-buffer) -----
constexpr int BM = 128, BN = 128, BK = 32;      // BK in halves
constexpr int NSTG = 4;
constexpr int AS = 40;                          // A smem stride (halves), LDSM conflict-free
constexpr int BS = 136;                         // B smem stride (halves), LDSM conflict-free
constexpr int A_HELE = BM * AS;                 // 5120
constexpr int B_HELE = BK * BS;                 // 4352
constexpr int GEMM_SMEM_BYTES = NSTG * (A_HELE + B_HELE) * 2;    // 75776

// OUT_MODE: 0 = fp32 store, 1 = fp16 store, 2 = fused weighted atomic combine
template<bool DO_GELU, int OUT_MODE, bool GATHER, bool EXPERT>
__global__ __launch_bounds__(256, 1)
void gemm_f16_kernel(const __half* __restrict__ A,
                     const __half* __restrict__ Bbase,
                     const float* __restrict__ biasBase,
                     void* __restrict__ Cv,
                     int N, int Kdim,
                     const int* __restrict__ perm,
                     const int* __restrict__ tile_expert,
                     long strideB, int strideBias,
                     const float* __restrict__ wslot)
{
    extern __shared__ __half smem[];
    __half* As = smem;                          // [NSTG][A_HELE]
    __half* Bs = smem + NSTG * A_HELE;          // [NSTG][B_HELE]

    const int mtile = blockIdx.y;
    const int ntile = blockIdx.x;

    const __half* Bp  = Bbase;
    const float* bias = biasBase;
    if (EXPERT) {
        int e = tile_expert[mtile];
        if (e < 0) return;
        Bp   += (long)e * strideB;
        bias += (long)e * strideBias;
    }

    const int tid   = threadIdx.x;
    const int lane  = tid & 31;
    const int warp  = tid >> 5;
    const int warpM = warp & 1;                 // 0..1 (64 rows each)
    const int warpN = warp >> 1;                // 0..3 (32 cols each)
    const int mbase = mtile * BM;
    const int nbase = ntile * BN;

    float acc[4][4][4];
    #pragma unroll
    for (int mi = 0; mi < 4; mi++)
        #pragma unroll
        for (int ni = 0; ni < 4; ni++)
            #pragma unroll
            for (int r = 0; r < 4; r++) acc[mi][ni][r] = 0.0f;

    const int KT = Kdim / BK;

    // ---- hoisted load state: global pointers + smem dst (uint32) ----
    const __half* aptr[2];
    uint32_t adst[2];
    #pragma unroll
    for (int i = 0; i < 2; i++) {
        int c = tid + i * 256;
        int r = c >> 2;
        int off = (c & 3) * 8;
        adst[i] = smem_u32(&As[r * AS + off]);
        if (GATHER) {
            int g = perm[mbase + r];
            if (g < 0) g = 0;                   // pad rows: any valid row (output discarded)
            aptr[i] = A + (long)g * Kdim + off;
        } else {
            aptr[i] = A + (long)(mbase + r) * Kdim + off;
        }
    }
    const __half* bptr[2];
    uint32_t bdst[2];
    #pragma unroll
    for (int i = 0; i < 2; i++) {
        int c = tid + i * 256;
        int r = c >> 4;
        int off = (c & 15) * 8;
        bdst[i] = smem_u32(&Bs[r * BS + off]);
        bptr[i] = Bp + (long)r * N + nbase + off;
    }
    const long bstep = (long)BK * N;

    auto load_tiles = [&](int stage) {
        const uint32_t soA = stage * (A_HELE * 2);
        const uint32_t soB = stage * (B_HELE * 2);
        #pragma unroll
        for (int i = 0; i < 2; i++) {
            cp_async16_ca(adst[i] + soA, aptr[i]);
            aptr[i] += BK;
        }
        #pragma unroll
        for (int i = 0; i < 2; i++) {
            cp_async16_cg(bdst[i] + soB, bptr[i]);
            bptr[i] += bstep;
        }
        asm volatile("cp.async.commit_group;\n" ::: "memory");
    };

    const uint32_t as_u = smem_u32(As);
    const uint32_t bs_u = smem_u32(Bs);
    const int tl = lane >> 3;
    const int lr = lane & 7;
    const int a_row0 = warpM * 64 + (tl & 1) * 8 + lr;
    const int a_col0 = (tl >> 1) * 8;
    const int b_krow0 = (tl & 1) * 8 + lr;
    const int b_col0  = warpN * 32 + (tl >> 1) * 8;

    // prefetch 3 slices
    load_tiles(0);
    load_tiles(1);
    load_tiles(2);

    for (int kt = 0; kt < KT; kt++) {
        // wait for slice kt: pending groups = min(3, KT-kt); wait until <= pending-1
        const int p = KT - kt - 1;
        if (p >= 2)      asm volatile("cp.async.wait_group 2;\n" ::: "memory");
        else if (p == 1) asm volatile("cp.async.wait_group 1;\n" ::: "memory");
        else             asm volatile("cp.async.wait_group 0;\n" ::: "memory");
        __syncthreads();                        // single barrier per K-slice

        // issue loads for slice kt+3 into stage (kt+3)&3 (== stage (kt-1)&3, reads done pre-barrier)
        if (kt + 3 < KT) load_tiles((kt + 3) & 3);

        const uint32_t asu = as_u + (kt & 3) * (A_HELE * 2);
        const uint32_t bsu = bs_u + (kt & 3) * (B_HELE * 2);

        // fragment double-buffer: batch all 12 LDSMs for both ks halves up front
        uint32_t a[2][4][4], b[2][4][2];
        #pragma unroll
        for (int ks = 0; ks < 2; ks++) {
            #pragma unroll
            for (int mi = 0; mi < 4; mi++)
                ldsm_x4(a[ks][mi][0], a[ks][mi][1], a[ks][mi][2], a[ks][mi][3],
                        asu + ((a_row0 + mi * 16) * AS + ks * 16 + a_col0) * 2);
            #pragma unroll
            for (int nj = 0; nj < 2; nj++)
                ldsm_x4_t(b[ks][2 * nj][0], b[ks][2 * nj][1],
                          b[ks][2 * nj + 1][0], b[ks][2 * nj + 1][1],
                          bsu + ((b_krow0 + ks * 16) * BS + b_col0 + nj * 16) * 2);
        }
        #pragma unroll
        for (int ks = 0; ks < 2; ks++)
            #pragma unroll
            for (int mi = 0; mi < 4; mi++)
                #pragma unroll
                for (int ni = 0; ni < 4; ni++)
                    mma_f16(acc[mi][ni], a[ks][mi][0], a[ks][mi][1], a[ks][mi][2], a[ks][mi][3],
                            b[ks][ni][0], b[ks][ni][1]);
    }

    // epilogue
    #pragma unroll
    for (int mi = 0; mi < 4; mi++) {
        const int r0 = mbase + warpM * 64 + mi * 16 + (lane >> 2);
        const int r1 = r0 + 8;
        int   g0 = 0, g1 = 0;
        float w0 = 0.0f, w1 = 0.0f;
        if (OUT_MODE == 2) {
            g0 = perm[r0]; g1 = perm[r1];
            w0 = wslot[r0]; w1 = wslot[r1];
        }
        #pragma unroll
        for (int ni = 0; ni < 4; ni++) {
            int col0 = nbase + warpN * 32 + ni * 8 + (lane & 3) * 2;
            float bv0 = bias[col0], bv1 = bias[col0 + 1];
            float v00 = acc[mi][ni][0] + bv0;
            float v01 = acc[mi][ni][1] + bv1;
            float v10 = acc[mi][ni][2] + bv0;
            float v11 = acc[mi][ni][3] + bv1;
            if (DO_GELU) {
                v00 = gelu_exact(v00); v01 = gelu_exact(v01);
                v10 = gelu_exact(v10); v11 = gelu_exact(v11);
            }
            if (OUT_MODE == 1) {
                __half* C = (__half*)Cv;
                *reinterpret_cast<__half2*>(C + (long)r0 * N + col0) = __floats2half2_rn(v00, v01);
                *reinterpret_cast<__half2*>(C + (long)r1 * N + col0) = __floats2half2_rn(v10, v11);
            } else if (OUT_MODE == 0) {
                float* C = (float*)Cv;
                *reinterpret_cast<float2*>(C + (long)r0 * N + col0) = make_float2(v00, v01);
                *reinterpret_cast<float2*>(C + (long)r1 * N + col0) = make_float2(v10, v11);
            } else {
                float* O = (float*)Cv;
                if (g0 >= 0) {
                    atomicAdd(&O[(long)g0 * N + col0    ], w0 * v00);
                    atomicAdd(&O[(long)g0 * N + col0 + 1], w0 * v01);
                }
                if (g1 >= 0) {
                    atomicAdd(&O[(long)g1 * N + col0    ], w1 * v10);
                    atomicAdd(&O[(long)g1 * N + col0 + 1], w1 * v11);
                }
            }
        }
    }
}

// ---------------- router GEMM: fp16 hi/lo split, 3 mma terms ----------------
constexpr int RAS = 40;
constexpr int RBS = 136;
constexpr int RA_HELE = BM * RAS;
constexpr int RB_HELE = BK * RBS;
constexpr int SPLIT_SMEM_BYTES = (4 * RA_HELE + 4 * RB_HELE) * 2;

__global__ __launch_bounds__(256, 2)
void gemm_split_f16_kernel(const __half* __restrict__ Ahi, const __half* __restrict__ Alo,
                           const __half* __restrict__ Bhi, const __half* __restrict__ Blo,
                           const float* __restrict__ bias,
                           float* __restrict__ C, int N, int Kdim)
{
    extern __shared__ __half hsmem[];
    __half* AsH = hsmem;
    __half* AsL = AsH + 2 * RA_HELE;
    __half* BsH = AsL + 2 * RA_HELE;
    __half* BsL = BsH + 2 * RB_HELE;

    const int mtile = blockIdx.y;
    const int ntile = blockIdx.x;
    const int tid   = threadIdx.x;
    const int lane  = tid & 31;
    const int warp  = tid >> 5;
    const int warpM = warp & 1;
    const int warpN = warp >> 1;
    const int mbase = mtile * BM;
    const int nbase = ntile * BN;

    float acc[4][4][4];
    #pragma unroll
    for (int mi = 0; mi < 4; mi++)
        #pragma unroll
        for (int ni = 0; ni < 4; ni++)
            #pragma unroll
            for (int r = 0; r < 4; r++) acc[mi][ni][r] = 0.0f;

    const int KT = Kdim / BK;

    auto load_tiles = [&](int kt, int stage) {
        const int k0 = kt * BK;
        #pragma unroll
        for (int i = 0; i < 2; i++) {
            int c   = tid + i * 256;
            int r   = c >> 2;
            int off = (c & 3) * 8;
            long go = (long)(mbase + r) * Kdim + k0 + off;
            cp_async16(&AsH[stage * RA_HELE + r * RAS + off], Ahi + go, 16);
            cp_async16(&AsL[stage * RA_HELE + r * RAS + off], Alo + go, 16);
        }
        #pragma unroll
        for (int i = 0; i < 2; i++) {
            int c   = tid + i * 256;
            int r   = c >> 4;
            int off = (c & 15) * 8;
            long go = (long)(k0 + r) * N + nbase + off;
            cp_async16(&BsH[stage * RB_HELE + r * RBS + off], Bhi + go, 16);
            cp_async16(&BsL[stage * RB_HELE + r * RBS + off], Blo + go, 16);
        }
        asm volatile("cp.async.commit_group;\n" ::: "memory");
    };

    const uint32_t ash_u = smem_u32(AsH);
    const uint32_t asl_u = smem_u32(AsL);
    const uint32_t bsh_u = smem_u32(BsH);
    const uint32_t bsl_u = smem_u32(BsL);
    const int tl = lane >> 3;
    const int lr = lane & 7;
    const int a_row0 = warpM * 64 + (tl & 1) * 8 + lr;
    const int a_col0 = (tl >> 1) * 8;
    const int b_krow0 = (tl & 1) * 8 + lr;
    const int b_col0  = warpN * 32 + (tl >> 1) * 8;

    load_tiles(0, 0);
    for (int kt = 0; kt < KT; kt++) {
        if (kt + 1 < KT) {
            load_tiles(kt + 1, (kt + 1) & 1);
            asm volatile("cp.async.wait_group 1;\n" ::: "memory");
        } else {
            asm volatile("cp.async.wait_group 0;\n" ::: "memory");
        }
        __syncthreads();

        const uint32_t ashu = ash_u + (kt & 1) * (RA_HELE * 2);
        const uint32_t aslu = asl_u + (kt & 1) * (RA_HELE * 2);
        const uint32_t bshu = bsh_u + (kt & 1) * (RB_HELE * 2);
        const uint32_t bslu = bsl_u + (kt & 1) * (RB_HELE * 2);

        #pragma unroll
        for (int ks = 0; ks < 2; ks++) {
            uint32_t ah[4][4], al[4][4];
            #pragma unroll
            for (int mi = 0; mi < 4; mi++) {
                uint32_t off = ((a_row0 + mi * 16) * RAS + ks * 16 + a_col0) * 2;
                ldsm_x4(ah[mi][0], ah[mi][1], ah[mi][2], ah[mi][3], ashu + off);
                ldsm_x4(al[mi][0], al[mi][1], al[mi][2], al[mi][3], aslu + off);
            }
            uint32_t bh[4][2], bl[4][2];
            #pragma unroll
            for (int nj = 0; nj < 2; nj++) {
                uint32_t off = ((b_krow0 + ks * 16) * RBS + b_col0 + nj * 16) * 2;
                ldsm_x4_t(bh[2 * nj][0], bh[2 * nj][1], bh[2 * nj + 1][0], bh[2 * nj + 1][1], bshu + off);
                ldsm_x4_t(bl[2 * nj][0], bl[2 * nj][1], bl[2 * nj + 1][0], bl[2 * nj + 1][1], bslu + off);
            }
            #pragma unroll
            for (int mi = 0; mi < 4; mi++)
                #pragma unroll
                for (int ni = 0; ni < 4; ni++) {
                    mma_f16(acc[mi][ni], ah[mi][0], ah[mi][1], ah[mi][2], ah[mi][3],
                            bl[ni][0], bl[ni][1]);
                    mma_f16(acc[mi][ni], al[mi][0], al[mi][1], al[mi][2], al[mi][3],
                            bh[ni][0], bh[ni][1]);
                    mma_f16(acc[mi][ni], ah[mi][0], ah[mi][1], ah[mi][2], ah[mi][3],
                            bh[ni][0], bh[ni][1]);
                }
        }
        __syncthreads();
    }

    #pragma unroll
    for (int mi = 0; mi < 4; mi++) {
        #pragma unroll
        for (int ni = 0; ni < 4; ni++) {
            int row0 = mbase + warpM * 64 + mi * 16 + (lane >> 2);
            int col0 = nbase + warpN * 32 + ni * 8 + (lane & 3) * 2;
            float bv0 = bias[col0], bv1 = bias[col0 + 1];
            float v00 = gelu_exact(acc[mi][ni][0] + bv0);
            float v01 = gelu_exact(acc[mi][ni][1] + bv1);
            float v10 = gelu_exact(acc[mi][ni][2] + bv0);
            float v11 = gelu_exact(acc[mi][ni][3] + bv1);
            *reinterpret_cast<float2*>(&C[(long)(row0    ) * N + col0]) = make_float2(v00, v01);
            *reinterpret_cast<float2*>(&C[(long)(row0 + 8) * N + col0]) = make_float2(v10, v11);
        }
    }
}

// ---------------- prep: init + fp16 conversions ----------------
__global__ void prep_kernel(const float4* __restrict__ W1, const float4* __restrict__ W2,
                            const float4* __restrict__ x,  const float4* __restrict__ Wr1,
                            __half* __restrict__ W1h, __half* __restrict__ W2h,
                            __half* __restrict__ xh,  __half* __restrict__ xl,
                            __half* __restrict__ wh,  __half* __restrict__ wl,
                            int* __restrict__ perm, int* __restrict__ counts,
                            int* __restrict__ done)
{
    long i = (long)blockIdx.x * 256 + threadIdx.x;
    if (i < MPAD)  perm[i] = -1;
    if (i < E_EXP) counts[i] = 0;
    if (i == 0)    *done = 0;

    if (i < W1E / 4) {
        float4 v = W1[i];
        __half2* p = reinterpret_cast<__half2*>(W1h + i * 4);
        p[0] = __floats2half2_rn(v.x, v.y);
        p[1] = __floats2half2_rn(v.z, v.w);
    } else if (i < (W1E + W2E) / 4) {
        long j = i - W1E / 4;
        float4 v = W2[j];
        __half2* p = reinterpret_cast<__half2*>(W2h + j * 4);
        p[0] = __floats2half2_rn(v.x, v.y);
        p[1] = __floats2half2_rn(v.z, v.w);
    } else if (i < (W1E + W2E + XE) / 4) {
        long j = i - (W1E + W2E) / 4;
        float4 v = x[j];
        __half h0 = __float2half_rn(v.x), h1 = __float2half_rn(v.y);
        __half h2 = __float2half_rn(v.z), h3 = __float2half_rn(v.w);
        __half2* ph = reinterpret_cast<__half2*>(xh + j * 4);
        ph[0] = __halves2half2(h0, h1);
        ph[1] = __halves2half2(h2, h3);
        __half2* pl = reinterpret_cast<__half2*>(xl + j * 4);
        pl[0] = __floats2half2_rn(v.x - __half2float(h0), v.y - __half2float(h1));
        pl[1] = __floats2half2_rn(v.z - __half2float(h2), v.w - __half2float(h3));
    } else if (i < (W1E + W2E + XE + WR1E) / 4) {
        long j = i - (W1E + W2E + XE) / 4;
        float4 v = Wr1[j];
        __half h0 = __float2half_rn(v.x), h1 = __float2half_rn(v.y);
        __half h2 = __float2half_rn(v.z), h3 = __float2half_rn(v.w);
        __half2* ph = reinterpret_cast<__half2*>(wh + j * 4);
        ph[0] = __halves2half2(h0, h1);
        ph[1] = __halves2half2(h2, h3);
        __half2* pl = reinterpret_cast<__half2*>(wl + j * 4);
        pl[0] = __floats2half2_rn(v.x - __half2float(h0), v.y - __half2float(h1));
        pl[1] = __floats2half2_rn(v.z - __half2float(h2), v.w - __half2float(h3));
    }
}

// ---------------- route: logits + softmax + top-2 + (last block) scan/fill --
__global__ void route_kernel(const float* __restrict__ H1,
                             const float* __restrict__ Wr2,
                             const float* __restrict__ br2,
                             int*   __restrict__ topk_idx,
                             float* __restrict__ topk_w,
                             int*   __restrict__ counts,
                             int*   __restrict__ done,
                             int*   __restrict__ perm,
                             int*   __restrict__ slot,
                             float* __restrict__ wslot,
                             int*   __restrict__ tile_expert)
{
    int warp = threadIdx.x >> 5, lane = threadIdx.x & 31;
    int t = blockIdx.x * 8 + warp;
    const float* h = H1 + (long)t * D_DIM;

    float acc[E_EXP];
    #pragma unroll
    for (int e = 0; e < E_EXP; e++) acc[e] = 0.0f;

    #pragma unroll 4
    for (int i = 0; i < D_DIM / 32; i++) {
        int d = i * 32 + lane;
        float hv = h[d];
        const float4* w4 = reinterpret_cast<const float4*>(Wr2 + (long)d * E_EXP);
        float4 wa = w4[0], wb = w4[1];
        acc[0] += hv * wa.x; acc[1] += hv * wa.y; acc[2] += hv * wa.z; acc[3] += hv * wa.w;
        acc[4] += hv * wb.x; acc[5] += hv * wb.y; acc[6] += hv * wb.z; acc[7] += hv * wb.w;
    }
    #pragma unroll
    for (int e = 0; e < E_EXP; e++)
        #pragma unroll
        for (int off = 16; off; off >>= 1)
            acc[e] += __shfl_xor_sync(0xFFFFFFFFu, acc[e], off);

    if (lane == 0) {
        float l[E_EXP];
        #pragma unroll
        for (int e = 0; e < E_EXP; e++) l[e] = acc[e] + br2[e];
        int e0 = 0;
        #pragma unroll
        for (int e = 1; e < E_EXP; e++) if (l[e] > l[e0]) e0 = e;
        int e1 = -1;
        #pragma unroll
        for (int e = 0; e < E_EXP; e++)
            if (e != e0 && (e1 < 0 || l[e] > l[e1])) e1 = e;
        float m  = l[e0];
        float p0 = expf(l[e0] - m);
        float p1 = expf(l[e1] - m);
        float inv = 1.0f / (p0 + p1);
        topk_idx[t * 2]     = e0;
        topk_idx[t * 2 + 1] = e1;
        topk_w[t * 2]       = p0 * inv;
        topk_w[t * 2 + 1]   = p1 * inv;
        atomicAdd(&counts[e0], 1);
        atomicAdd(&counts[e1], 1);
    }

    __syncthreads();
    __shared__ int is_last;
    if (threadIdx.x == 0) {
        __threadfence();
        int prev = atomicAdd(done, 1);
        is_last = (prev == (int)gridDim.x - 1);
    }
    __syncthreads();
    if (!is_last) return;
    __threadfence();

    __shared__ int s_off[E_EXP + 1];
    __shared__ int s_fill[E_EXP];
    if (threadIdx.x == 0) {
        int off = 0;
        for (int e = 0; e < E_EXP; e++) {
            s_off[e] = off;
            off += (counts[e] + 127) & ~127;
        }
        s_off[E_EXP] = off;
        int e = 0;
        for (int tile = 0; tile < MTILES; tile++) {
            int r = tile * 128;
            if (r >= off) { tile_expert[tile] = -1; continue; }
            while (e < E_EXP && r >= s_off[e + 1]) e++;
            tile_expert[tile] = e;
        }
    }
    if (threadIdx.x < E_EXP) s_fill[threadIdx.x] = 0;
    __syncthreads();

    for (int tt = threadIdx.x; tt < T_TOK; tt += 256) {
        #pragma unroll
        for (int k = 0; k < 2; k++) {
            int e   = topk_idx[tt * 2 + k];
            int pos = s_off[e] + atomicAdd(&s_fill[e], 1);
            perm[pos]        = tt;
            slot[tt * 2 + k] = pos;
            wslot[pos]       = topk_w[tt * 2 + k];
        }
    }
}

// ---------------- launch ----------------
extern "C" void kernel_launch(void* const* d_in, const int* in_sizes, int n_in,
                              void* d_out, int out_size)
{
    const float* x   = (const float*)d_in[0];
    const float* Wr1 = (const float*)d_in[1];
    const float* br1 = (const float*)d_in[2];
    const float* Wr2 = (const float*)d_in[3];
    const float* br2 = (const float*)d_in[4];
    const float* W1  = (const float*)d_in[5];
    const float* b1  = (const float*)d_in[6];
    const float* W2  = (const float*)d_in[7];
    const float* b2  = (const float*)d_in[8];
    float* out = (float*)d_out;

    void *pH1, *ph, *pW1h, *pW2h, *pxh, *pxl, *pwh, *pwl;
    void *pti, *ptw, *pws, *pc, *pp, *ps, *pte, *pd;
    cudaGetSymbolAddress(&pH1,  g_H1);
    cudaGetSymbolAddress(&ph,   g_h);
    cudaGetSymbolAddress(&pW1h, g_W1h);
    cudaGetSymbolAddress(&pW2h, g_W2h);
    cudaGetSymbolAddress(&pxh,  g_xh);
    cudaGetSymbolAddress(&pxl,  g_xl);
    cudaGetSymbolAddress(&pwh,  g_wh);
    cudaGetSymbolAddress(&pwl,  g_wl);
    cudaGetSymbolAddress(&pti,  g_topk_idx);
    cudaGetSymbolAddress(&ptw,  g_topk_w);
    cudaGetSymbolAddress(&pws,  g_wslot);
    cudaGetSymbolAddress(&pc,   g_counts);
    cudaGetSymbolAddress(&pp,   g_perm);
    cudaGetSymbolAddress(&ps,   g_slot);
    cudaGetSymbolAddress(&pte,  g_tile_expert);
    cudaGetSymbolAddress(&pd,   g_done);

    cudaFuncSetAttribute(gemm_split_f16_kernel,
                         cudaFuncAttributeMaxDynamicSharedMemorySize, SPLIT_SMEM_BYTES);
    cudaFuncSetAttribute(gemm_f16_kernel<true,  1, true,  true>,
                         cudaFuncAttributeMaxDynamicSharedMemorySize, GEMM_SMEM_BYTES);
    cudaFuncSetAttribute(gemm_f16_kernel<false, 2, false, true>,
                         cudaFuncAttributeMaxDynamicSharedMemorySize, GEMM_SMEM_BYTES);

    // 0) prep: init + fp16 conversions; zero the output for fused atomic combine
    long nprep4 = (W1E + W2E + XE + WR1E) / 4;
    prep_kernel<<<(unsigned)((nprep4 + 255) / 256), 256>>>(
        (const float4*)W1, (const float4*)W2, (const float4*)x, (const float4*)Wr1,
        (__half*)pW1h, (__half*)pW2h, (__half*)pxh, (__half*)pxl,
        (__half*)pwh, (__half*)pwl,
        (int*)pp, (int*)pc, (int*)pd);
    cudaMemsetAsync(out, 0, (size_t)out_size * sizeof(float));

    // 1) router hidden: H1 = GELU(x @ Wr1 + br1), fp16 split (near-fp32)
    gemm_split_f16_kernel<<<dim3(D_DIM / BN, T_TOK / BM), 256, SPLIT_SMEM_BYTES>>>(
        (const __half*)pxh, (const __half*)pxl, (const __half*)pwh, (const __half*)pwl,
        br1, (float*)pH1, D_DIM, D_DIM);

    // 2) logits + softmax + top-2 + counts + scan + fill (+ per-slot weights)
    route_kernel<<<T_TOK / 8, 256>>>((const float*)pH1, Wr2, br2,
                                     (int*)pti, (float*)ptw, (int*)pc, (int*)pd,
                                     (int*)pp, (int*)ps, (float*)pws, (int*)pte);

    // 3) expert layer 1 (grouped, gathered): h = fp16(GELU(xh[perm] @ W1h + b1))
    gemm_f16_kernel<true, 1, true, true>
        <<<dim3(H_DIM / BN, MTILES), 256, GEMM_SMEM_BYTES>>>(
            (const __half*)pxh, (const __half*)pW1h, b1, ph, H_DIM, D_DIM,
            (const int*)pp, (const int*)pte, (long)D_DIM * H_DIM, H_DIM, nullptr);

    // 4) expert layer 2 + fused weighted combine:
    //    out[token] += wslot[slot] * (h[slot] @ W2h + b2)   (2 addends/element, order-invariant)
    gemm_f16_kernel<false, 2, false, true>
        <<<dim3(D_DIM / BN, MTILES), 256, GEMM_SMEM_BYTES>>>(
            (const __half*)ph, (const __half*)pW2h, b2, out, D_DIM, H_DIM,
            (const int*)pp, (const int*)pte, (long)H_DIM * D_DIM, D_DIM,
            (const float*)pws);
}

// round 10
// speedup vs baseline: 2.0020x; 2.0020x over previous
#include <cuda_runtime.h>
#include <cuda_fp16.h>
#include <cstdint>
#include <cmath>

// ---------------- problem constants ----------------
#define T_TOK  8192
#define D_DIM  1024
#define E_EXP  8
#define H_DIM  4096
#define MPAD   17408
#define MTILES 136

#define XE   8388608L
#define WR1E 1048576L
#define W1E  33554432L
#define W2E  33554432L

// ---------------- scratch ----------------
__device__ float  g_H1[(size_t)T_TOK * D_DIM];   // router hidden (fp32)
__device__ __half g_h [(size_t)MPAD * H_DIM];    // expert hidden (fp16)
__device__ __half g_W1h[W1E];                    // fp16(W1) [E][D][H]
__device__ __half g_W2h[W2E];                    // fp16(W2) [E][H][D]
__device__ __half g_xh[XE];
__device__ __half g_xl[XE];
__device__ __half g_wh[WR1E];
__device__ __half g_wl[WR1E];
__device__ int    g_topk_idx[T_TOK * 2];
__device__ float  g_topk_w [T_TOK * 2];
__device__ float  g_wslot  [MPAD];               // per-slot combine weight
__device__ int    g_counts [E_EXP];
__device__ int    g_perm   [MPAD];
__device__ int    g_slot   [T_TOK * 2];
__device__ int    g_tile_expert[MTILES];
__device__ int    g_done;

// ---------------- helpers ----------------
__device__ __forceinline__ float gelu_exact(float x) {
    return 0.5f * x * (1.0f + erff(x * 0.70710678118654752440f));
}
__device__ __forceinline__ void mma_f16(float c[4],
                                        uint32_t a0, uint32_t a1, uint32_t a2, uint32_t a3,
                                        uint32_t b0, uint32_t b1) {
    asm volatile(
        "mma.sync.aligned.m16n8k16.row.col.f32.f16.f16.f32 "
        "{%0,%1,%2,%3}, {%4,%5,%6,%7}, {%8,%9}, {%0,%1,%2,%3};\n"
        : "+f"(c[0]), "+f"(c[1]), "+f"(c[2]), "+f"(c[3])
        : "r"(a0), "r"(a1), "r"(a2), "r"(a3), "r"(b0), "r"(b1));
}
__device__ __forceinline__ void ldsm_x4(uint32_t& r0, uint32_t& r1, uint32_t& r2, uint32_t& r3,
                                        uint32_t addr) {
    asm volatile("ldmatrix.sync.aligned.m8n8.x4.shared.b16 {%0,%1,%2,%3}, [%4];"
                 : "=r"(r0), "=r"(r1), "=r"(r2), "=r"(r3) : "r"(addr));
}
__device__ __forceinline__ void ldsm_x4_t(uint32_t& r0, uint32_t& r1, uint32_t& r2, uint32_t& r3,
                                          uint32_t addr) {
    asm volatile("ldmatrix.sync.aligned.m8n8.x4.trans.shared.b16 {%0,%1,%2,%3}, [%4];"
                 : "=r"(r0), "=r"(r1), "=r"(r2), "=r"(r3) : "r"(addr));
}
__device__ __forceinline__ void cp_async16(void* smem_dst, const void* gmem_src, unsigned src_bytes) {
    unsigned d = (unsigned)__cvta_generic_to_shared(smem_dst);
    asm volatile("cp.async.ca.shared.global [%0], [%1], 16, %2;\n"
                 :: "r"(d), "l"(gmem_src), "r"(src_bytes) : "memory");
}
__device__ __forceinline__ void cp_async16_ca(uint32_t smem_dst, const void* gmem_src) {
    asm volatile("cp.async.ca.shared.global [%0], [%1], 16;\n"
                 :: "r"(smem_dst), "l"(gmem_src) : "memory");
}
__device__ __forceinline__ void cp_async16_cg(uint32_t smem_dst, const void* gmem_src) {
    asm volatile("cp.async.cg.shared.global [%0], [%1], 16;\n"
                 :: "r"(smem_dst), "l"(gmem_src) : "memory");
}
__device__ __forceinline__ uint32_t smem_u32(const void* p) {
    return (uint32_t)__cvta_generic_to_shared(p);
}

// ---------------- main GEMM tiling (BK=32, 4-stage, 2 barriers/slice) -------
constexpr int BM = 128, BN = 128, BK = 32;      // BK in halves
constexpr int NSTG = 4;
constexpr int AS = 40;                          // A smem stride (halves), LDSM conflict-free
constexpr int BS = 136;                         // B smem stride (halves), LDSM conflict-free
constexpr int A_HELE = BM * AS;                 // 5120
constexpr int B_HELE = BK * BS;                 // 4352
constexpr int GEMM_SMEM_BYTES = NSTG * (A_HELE + B_HELE) * 2;    // 75776

// OUT_MODE: 0 = fp32 store, 1 = fp16 store, 2 = fused weighted atomic combine
template<bool DO_GELU, int OUT_MODE, bool GATHER, bool EXPERT>
__global__ __launch_bounds__(256, 2)
void gemm_f16_kernel(const __half* __restrict__ A,
                     const __half* __restrict__ Bbase,
                     const float* __restrict__ biasBase,
                     void* __restrict__ Cv,
                     int N, int Kdim,
                     const int* __restrict__ perm,
                     const int* __restrict__ tile_expert,
                     long strideB, int strideBias,
                     const float* __restrict__ wslot)
{
    extern __shared__ __half smem[];
    __half* As = smem;                          // [NSTG][A_HELE]
    __half* Bs = smem + NSTG * A_HELE;          // [NSTG][B_HELE]

    const int mtile = blockIdx.y;
    const int ntile = blockIdx.x;

    const __half* Bp  = Bbase;
    const float* bias = biasBase;
    if (EXPERT) {
        int e = tile_expert[mtile];
        if (e < 0) return;
        Bp   += (long)e * strideB;
        bias += (long)e * strideBias;
    }

    const int tid   = threadIdx.x;
    const int lane  = tid & 31;
    const int warp  = tid >> 5;
    const int warpM = warp & 1;                 // 0..1 (64 rows each)
    const int warpN = warp >> 1;                // 0..3 (32 cols each)
    const int mbase = mtile * BM;
    const int nbase = ntile * BN;

    float acc[4][4][4];
    #pragma unroll
    for (int mi = 0; mi < 4; mi++)
        #pragma unroll
        for (int ni = 0; ni < 4; ni++)
            #pragma unroll
            for (int r = 0; r < 4; r++) acc[mi][ni][r] = 0.0f;

    const int KT = Kdim / BK;                   // always a multiple of 4 here (32 or 128)

    // ---- hoisted load state: global pointers + smem dst (uint32) ----
    const __half* aptr[2];
    uint32_t adst[2];
    #pragma unroll
    for (int i = 0; i < 2; i++) {
        int c = tid + i * 256;
        int r = c >> 2;
        int off = (c & 3) * 8;
        adst[i] = smem_u32(&As[r * AS + off]);
        if (GATHER) {
            int g = perm[mbase + r];
            if (g < 0) g = 0;                   // pad rows: any valid row (output discarded)
            aptr[i] = A + (long)g * Kdim + off;
        } else {
            aptr[i] = A + (long)(mbase + r) * Kdim + off;
        }
    }
    const __half* bptr[2];
    uint32_t bdst[2];
    #pragma unroll
    for (int i = 0; i < 2; i++) {
        int c = tid + i * 256;
        int r = c >> 4;
        int off = (c & 15) * 8;
        bdst[i] = smem_u32(&Bs[r * BS + off]);
        bptr[i] = Bp + (long)r * N + nbase + off;
    }
    const long bstep = (long)BK * N;

    auto load_tiles = [&](int stage) {          // stage is compile-time const at call sites
        const uint32_t soA = stage * (A_HELE * 2);
        const uint32_t soB = stage * (B_HELE * 2);
        #pragma unroll
        for (int i = 0; i < 2; i++) {
            cp_async16_ca(adst[i] + soA, aptr[i]);
            aptr[i] += BK;
        }
        #pragma unroll
        for (int i = 0; i < 2; i++) {
            cp_async16_cg(bdst[i] + soB, bptr[i]);
            bptr[i] += bstep;
        }
        asm volatile("cp.async.commit_group;\n" ::: "memory");
    };

    const uint32_t as_u = smem_u32(As);
    const uint32_t bs_u = smem_u32(Bs);
    const int tl = lane >> 3;
    const int lr = lane & 7;
    const int a_row0 = warpM * 64 + (tl & 1) * 8 + lr;
    const int a_col0 = (tl >> 1) * 8;
    const int b_krow0 = (tl & 1) * 8 + lr;
    const int b_col0  = warpN * 32 + (tl >> 1) * 8;

    auto compute_stage = [&](int stage) {       // stage compile-time const at call sites
        const uint32_t asu = as_u + stage * (A_HELE * 2);
        const uint32_t bsu = bs_u + stage * (B_HELE * 2);
        #pragma unroll
        for (int ks = 0; ks < 2; ks++) {
            uint32_t a[4][4];
            #pragma unroll
            for (int mi = 0; mi < 4; mi++)
                ldsm_x4(a[mi][0], a[mi][1], a[mi][2], a[mi][3],
                        asu + ((a_row0 + mi * 16) * AS + ks * 16 + a_col0) * 2);
            uint32_t b[4][2];
            #pragma unroll
            for (int nj = 0; nj < 2; nj++)
                ldsm_x4_t(b[2 * nj][0], b[2 * nj][1], b[2 * nj + 1][0], b[2 * nj + 1][1],
                          bsu + ((b_krow0 + ks * 16) * BS + b_col0 + nj * 16) * 2);
            #pragma unroll
            for (int mi = 0; mi < 4; mi++)
                #pragma unroll
                for (int ni = 0; ni < 4; ni++)
                    mma_f16(acc[mi][ni], a[mi][0], a[mi][1], a[mi][2], a[mi][3],
                            b[ni][0], b[ni][1]);
        }
    };

    // prologue: prefetch 3 slices (KT >= 4 always)
    load_tiles(0);
    load_tiles(1);
    load_tiles(2);

    for (int kt = 0; kt < KT; kt += 4) {
        #pragma unroll
        for (int u = 0; u < 4; u++) {
            const int k = kt + u;
            // outstanding groups before compute of slice k: min(3, KT - k)
            const int p = (KT - k) < 3 ? (KT - k) : 3;
            if (p == 3)      asm volatile("cp.async.wait_group 2;\n" ::: "memory");
            else if (p == 2) asm volatile("cp.async.wait_group 1;\n" ::: "memory");
            else             asm volatile("cp.async.wait_group 0;\n" ::: "memory");
            __syncthreads();
            compute_stage(u);
            __syncthreads();
            if (k + 3 < KT) load_tiles((u + 3) & 3);   // stage (k+3)&3, reads of it finished pre-barrier
        }
    }

    // epilogue
    #pragma unroll
    for (int mi = 0; mi < 4; mi++) {
        const int r0 = mbase + warpM * 64 + mi * 16 + (lane >> 2);
        const int r1 = r0 + 8;
        int   g0 = 0, g1 = 0;
        float w0 = 0.0f, w1 = 0.0f;
        if (OUT_MODE == 2) {
            g0 = perm[r0]; g1 = perm[r1];
            w0 = wslot[r0]; w1 = wslot[r1];
        }
        #pragma unroll
        for (int ni = 0; ni < 4; ni++) {
            int col0 = nbase + warpN * 32 + ni * 8 + (lane & 3) * 2;
            float bv0 = bias[col0], bv1 = bias[col0 + 1];
            float v00 = acc[mi][ni][0] + bv0;
            float v01 = acc[mi][ni][1] + bv1;
            float v10 = acc[mi][ni][2] + bv0;
            float v11 = acc[mi][ni][3] + bv1;
            if (DO_GELU) {
                v00 = gelu_exact(v00); v01 = gelu_exact(v01);
                v10 = gelu_exact(v10); v11 = gelu_exact(v11);
            }
            if (OUT_MODE == 1) {
                __half* C = (__half*)Cv;
                *reinterpret_cast<__half2*>(C + (long)r0 * N + col0) = __floats2half2_rn(v00, v01);
                *reinterpret_cast<__half2*>(C + (long)r1 * N + col0) = __floats2half2_rn(v10, v11);
            } else if (OUT_MODE == 0) {
                float* C = (float*)Cv;
                *reinterpret_cast<float2*>(C + (long)r0 * N + col0) = make_float2(v00, v01);
                *reinterpret_cast<float2*>(C + (long)r1 * N + col0) = make_float2(v10, v11);
            } else {
                float* O = (float*)Cv;
                if (g0 >= 0) {
                    atomicAdd(&O[(long)g0 * N + col0    ], w0 * v00);
                    atomicAdd(&O[(long)g0 * N + col0 + 1], w0 * v01);
                }
                if (g1 >= 0) {
                    atomicAdd(&O[(long)g1 * N + col0    ], w1 * v10);
                    atomicAdd(&O[(long)g1 * N + col0 + 1], w1 * v11);
                }
            }
        }
    }
}

// ---------------- router GEMM: fp16 hi/lo split, 3 mma terms ----------------
constexpr int RAS = 40;
constexpr int RBS = 136;
constexpr int RA_HELE = BM * RAS;
constexpr int RB_HELE = BK * RBS;
constexpr int SPLIT_SMEM_BYTES = (4 * RA_HELE + 4 * RB_HELE) * 2;

__global__ __launch_bounds__(256, 2)
void gemm_split_f16_kernel(const __half* __restrict__ Ahi, const __half* __restrict__ Alo,
                           const __half* __restrict__ Bhi, const __half* __restrict__ Blo,
                           const float* __restrict__ bias,
                           float* __restrict__ C, int N, int Kdim)
{
    extern __shared__ __half hsmem[];
    __half* AsH = hsmem;
    __half* AsL = AsH + 2 * RA_HELE;
    __half* BsH = AsL + 2 * RA_HELE;
    __half* BsL = BsH + 2 * RB_HELE;

    const int mtile = blockIdx.y;
    const int ntile = blockIdx.x;
    const int tid   = threadIdx.x;
    const int lane  = tid & 31;
    const int warp  = tid >> 5;
    const int warpM = warp & 1;
    const int warpN = warp >> 1;
    const int mbase = mtile * BM;
    const int nbase = ntile * BN;

    float acc[4][4][4];
    #pragma unroll
    for (int mi = 0; mi < 4; mi++)
        #pragma unroll
        for (int ni = 0; ni < 4; ni++)
            #pragma unroll
            for (int r = 0; r < 4; r++) acc[mi][ni][r] = 0.0f;

    const int KT = Kdim / BK;

    auto load_tiles = [&](int kt, int stage) {
        const int k0 = kt * BK;
        #pragma unroll
        for (int i = 0; i < 2; i++) {
            int c   = tid + i * 256;
            int r   = c >> 2;
            int off = (c & 3) * 8;
            long go = (long)(mbase + r) * Kdim + k0 + off;
            cp_async16(&AsH[stage * RA_HELE + r * RAS + off], Ahi + go, 16);
            cp_async16(&AsL[stage * RA_HELE + r * RAS + off], Alo + go, 16);
        }
        #pragma unroll
        for (int i = 0; i < 2; i++) {
            int c   = tid + i * 256;
            int r   = c >> 4;
            int off = (c & 15) * 8;
            long go = (long)(k0 + r) * N + nbase + off;
            cp_async16(&BsH[stage * RB_HELE + r * RBS + off], Bhi + go, 16);
            cp_async16(&BsL[stage * RB_HELE + r * RBS + off], Blo + go, 16);
        }
        asm volatile("cp.async.commit_group;\n" ::: "memory");
    };

    const uint32_t ash_u = smem_u32(AsH);
    const uint32_t asl_u = smem_u32(AsL);
    const uint32_t bsh_u = smem_u32(BsH);
    const uint32_t bsl_u = smem_u32(BsL);
    const int tl = lane >> 3;
    const int lr = lane & 7;
    const int a_row0 = warpM * 64 + (tl & 1) * 8 + lr;
    const int a_col0 = (tl >> 1) * 8;
    const int b_krow0 = (tl & 1) * 8 + lr;
    const int b_col0  = warpN * 32 + (tl >> 1) * 8;

    load_tiles(0, 0);
    for (int kt = 0; kt < KT; kt++) {
        if (kt + 1 < KT) {
            load_tiles(kt + 1, (kt + 1) & 1);
            asm volatile("cp.async.wait_group 1;\n" ::: "memory");
        } else {
            asm volatile("cp.async.wait_group 0;\n" ::: "memory");
        }
        __syncthreads();

        const uint32_t ashu = ash_u + (kt & 1) * (RA_HELE * 2);
        const uint32_t aslu = asl_u + (kt & 1) * (RA_HELE * 2);
        const uint32_t bshu = bsh_u + (kt & 1) * (RB_HELE * 2);
        const uint32_t bslu = bsl_u + (kt & 1) * (RB_HELE * 2);

        #pragma unroll
        for (int ks = 0; ks < 2; ks++) {
            uint32_t ah[4][4], al[4][4];
            #pragma unroll
            for (int mi = 0; mi < 4; mi++) {
                uint32_t off = ((a_row0 + mi * 16) * RAS + ks * 16 + a_col0) * 2;
                ldsm_x4(ah[mi][0], ah[mi][1], ah[mi][2], ah[mi][3], ashu + off);
                ldsm_x4(al[mi][0], al[mi][1], al[mi][2], al[mi][3], aslu + off);
            }
            uint32_t bh[4][2], bl[4][2];
            #pragma unroll
            for (int nj = 0; nj < 2; nj++) {
                uint32_t off = ((b_krow0 + ks * 16) * RBS + b_col0 + nj * 16) * 2;
                ldsm_x4_t(bh[2 * nj][0], bh[2 * nj][1], bh[2 * nj + 1][0], bh[2 * nj + 1][1], bshu + off);
                ldsm_x4_t(bl[2 * nj][0], bl[2 * nj][1], bl[2 * nj + 1][0], bl[2 * nj + 1][1], bslu + off);
            }
            #pragma unroll
            for (int mi = 0; mi < 4; mi++)
                #pragma unroll
                for (int ni = 0; ni < 4; ni++) {
                    mma_f16(acc[mi][ni], ah[mi][0], ah[mi][1], ah[mi][2], ah[mi][3],
                            bl[ni][0], bl[ni][1]);
                    mma_f16(acc[mi][ni], al[mi][0], al[mi][1], al[mi][2], al[mi][3],
                            bh[ni][0], bh[ni][1]);
                    mma_f16(acc[mi][ni], ah[mi][0], ah[mi][1], ah[mi][2], ah[mi][3],
                            bh[ni][0], bh[ni][1]);
                }
        }
        __syncthreads();
    }

    #pragma unroll
    for (int mi = 0; mi < 4; mi++) {
        #pragma unroll
        for (int ni = 0; ni < 4; ni++) {
            int row0 = mbase + warpM * 64 + mi * 16 + (lane >> 2);
            int col0 = nbase + warpN * 32 + ni * 8 + (lane & 3) * 2;
            float bv0 = bias[col0], bv1 = bias[col0 + 1];
            float v00 = gelu_exact(acc[mi][ni][0] + bv0);
            float v01 = gelu_exact(acc[mi][ni][1] + bv1);
            float v10 = gelu_exact(acc[mi][ni][2] + bv0);
            float v11 = gelu_exact(acc[mi][ni][3] + bv1);
            *reinterpret_cast<float2*>(&C[(long)(row0    ) * N + col0]) = make_float2(v00, v01);
            *reinterpret_cast<float2*>(&C[(long)(row0 + 8) * N + col0]) = make_float2(v10, v11);
        }
    }
}

// ---------------- prep: init + fp16 conversions ----------------
__global__ void prep_kernel(const float4* __restrict__ W1, const float4* __restrict__ W2,
                            const float4* __restrict__ x,  const float4* __restrict__ Wr1,
                            __half* __restrict__ W1h, __half* __restrict__ W2h,
                            __half* __restrict__ xh,  __half* __restrict__ xl,
                            __half* __restrict__ wh,  __half* __restrict__ wl,
                            int* __restrict__ perm, int* __restrict__ counts,
                            int* __restrict__ done)
{
    long i = (long)blockIdx.x * 256 + threadIdx.x;
    if (i < MPAD)  perm[i] = -1;
    if (i < E_EXP) counts[i] = 0;
    if (i == 0)    *done = 0;

    if (i < W1E / 4) {
        float4 v = W1[i];
        __half2* p = reinterpret_cast<__half2*>(W1h + i * 4);
        p[0] = __floats2half2_rn(v.x, v.y);
        p[1] = __floats2half2_rn(v.z, v.w);
    } else if (i < (W1E + W2E) / 4) {
        long j = i - W1E / 4;
        float4 v = W2[j];
        __half2* p = reinterpret_cast<__half2*>(W2h + j * 4);
        p[0] = __floats2half2_rn(v.x, v.y);
        p[1] = __floats2half2_rn(v.z, v.w);
    } else if (i < (W1E + W2E + XE) / 4) {
        long j = i - (W1E + W2E) / 4;
        float4 v = x[j];
        __half h0 = __float2half_rn(v.x), h1 = __float2half_rn(v.y);
        __half h2 = __float2half_rn(v.z), h3 = __float2half_rn(v.w);
        __half2* ph = reinterpret_cast<__half2*>(xh + j * 4);
        ph[0] = __halves2half2(h0, h1);
        ph[1] = __halves2half2(h2, h3);
        __half2* pl = reinterpret_cast<__half2*>(xl + j * 4);
        pl[0] = __floats2half2_rn(v.x - __half2float(h0), v.y - __half2float(h1));
        pl[1] = __floats2half2_rn(v.z - __half2float(h2), v.w - __half2float(h3));
    } else if (i < (W1E + W2E + XE + WR1E) / 4) {
        long j = i - (W1E + W2E + XE) / 4;
        float4 v = Wr1[j];
        __half h0 = __float2half_rn(v.x), h1 = __float2half_rn(v.y);
        __half h2 = __float2half_rn(v.z), h3 = __float2half_rn(v.w);
        __half2* ph = reinterpret_cast<__half2*>(wh + j * 4);
        ph[0] = __halves2half2(h0, h1);
        ph[1] = __halves2half2(h2, h3);
        __half2* pl = reinterpret_cast<__half2*>(wl + j * 4);
        pl[0] = __floats2half2_rn(v.x - __half2float(h0), v.y - __half2float(h1));
        pl[1] = __floats2half2_rn(v.z - __half2float(h2), v.w - __half2float(h3));
    }
}

// ---------------- route: logits + softmax + top-2 + (last block) scan/fill --
__global__ void route_kernel(const float* __restrict__ H1,
                             const float* __restrict__ Wr2,
                             const float* __restrict__ br2,
                             int*   __restrict__ topk_idx,
                             float* __restrict__ topk_w,
                             int*   __restrict__ counts,
                             int*   __restrict__ done,
                             int*   __restrict__ perm,
                             int*   __restrict__ slot,
                             float* __restrict__ wslot,
                             int*   __restrict__ tile_expert)
{
    int warp = threadIdx.x >> 5, lane = threadIdx.x & 31;
    int t = blockIdx.x * 8 + warp;
    const float* h = H1 + (long)t * D_DIM;

    float acc[E_EXP];
    #pragma unroll
    for (int e = 0; e < E_EXP; e++) acc[e] = 0.0f;

    #pragma unroll 4
    for (int i = 0; i < D_DIM / 32; i++) {
        int d = i * 32 + lane;
        float hv = h[d];
        const float4* w4 = reinterpret_cast<const float4*>(Wr2 + (long)d * E_EXP);
        float4 wa = w4[0], wb = w4[1];
        acc[0] += hv * wa.x; acc[1] += hv * wa.y; acc[2] += hv * wa.z; acc[3] += hv * wa.w;
        acc[4] += hv * wb.x; acc[5] += hv * wb.y; acc[6] += hv * wb.z; acc[7] += hv * wb.w;
    }
    #pragma unroll
    for (int e = 0; e < E_EXP; e++)
        #pragma unroll
        for (int off = 16; off; off >>= 1)
            acc[e] += __shfl_xor_sync(0xFFFFFFFFu, acc[e], off);

    if (lane == 0) {
        float l[E_EXP];
        #pragma unroll
        for (int e = 0; e < E_EXP; e++) l[e] = acc[e] + br2[e];
        int e0 = 0;
        #pragma unroll
        for (int e = 1; e < E_EXP; e++) if (l[e] > l[e0]) e0 = e;
        int e1 = -1;
        #pragma unroll
        for (int e = 0; e < E_EXP; e++)
            if (e != e0 && (e1 < 0 || l[e] > l[e1])) e1 = e;
        float m  = l[e0];
        float p0 = expf(l[e0] - m);
        float p1 = expf(l[e1] - m);
        float inv = 1.0f / (p0 + p1);
        topk_idx[t * 2]     = e0;
        topk_idx[t * 2 + 1] = e1;
        topk_w[t * 2]       = p0 * inv;
        topk_w[t * 2 + 1]   = p1 * inv;
        atomicAdd(&counts[e0], 1);
        atomicAdd(&counts[e1], 1);
    }

    __syncthreads();
    __shared__ int is_last;
    if (threadIdx.x == 0) {
        __threadfence();
        int prev = atomicAdd(done, 1);
        is_last = (prev == (int)gridDim.x - 1);
    }
    __syncthreads();
    if (!is_last) return;
    __threadfence();

    __shared__ int s_off[E_EXP + 1];
    __shared__ int s_fill[E_EXP];
    if (threadIdx.x == 0) {
        int off = 0;
        for (int e = 0; e < E_EXP; e++) {
            s_off[e] = off;
            off += (counts[e] + 127) & ~127;
        }
        s_off[E_EXP] = off;
        int e = 0;
        for (int tile = 0; tile < MTILES; tile++) {
            int r = tile * 128;
            if (r >= off) { tile_expert[tile] = -1; continue; }
            while (e < E_EXP && r >= s_off[e + 1]) e++;
            tile_expert[tile] = e;
        }
    }
    if (threadIdx.x < E_EXP) s_fill[threadIdx.x] = 0;
    __syncthreads();

    for (int tt = threadIdx.x; tt < T_TOK; tt += 256) {
        #pragma unroll
        for (int k = 0; k < 2; k++) {
            int e   = topk_idx[tt * 2 + k];
            int pos = s_off[e] + atomicAdd(&s_fill[e], 1);
            perm[pos]        = tt;
            slot[tt * 2 + k] = pos;
            wslot[pos]       = topk_w[tt * 2 + k];
        }
    }
}

// ---------------- launch ----------------
extern "C" void kernel_launch(void* const* d_in, const int* in_sizes, int n_in,
                              void* d_out, int out_size)
{
    const float* x   = (const float*)d_in[0];
    const float* Wr1 = (const float*)d_in[1];
    const float* br1 = (const float*)d_in[2];
    const float* Wr2 = (const float*)d_in[3];
    const float* br2 = (const float*)d_in[4];
    const float* W1  = (const float*)d_in[5];
    const float* b1  = (const float*)d_in[6];
    const float* W2  = (const float*)d_in[7];
    const float* b2  = (const float*)d_in[8];
    float* out = (float*)d_out;

    void *pH1, *ph, *pW1h, *pW2h, *pxh, *pxl, *pwh, *pwl;
    void *pti, *ptw, *pws, *pc, *pp, *ps, *pte, *pd;
    cudaGetSymbolAddress(&pH1,  g_H1);
    cudaGetSymbolAddress(&ph,   g_h);
    cudaGetSymbolAddress(&pW1h, g_W1h);
    cudaGetSymbolAddress(&pW2h, g_W2h);
    cudaGetSymbolAddress(&pxh,  g_xh);
    cudaGetSymbolAddress(&pxl,  g_xl);
    cudaGetSymbolAddress(&pwh,  g_wh);
    cudaGetSymbolAddress(&pwl,  g_wl);
    cudaGetSymbolAddress(&pti,  g_topk_idx);
    cudaGetSymbolAddress(&ptw,  g_topk_w);
    cudaGetSymbolAddress(&pws,  g_wslot);
    cudaGetSymbolAddress(&pc,   g_counts);
    cudaGetSymbolAddress(&pp,   g_perm);
    cudaGetSymbolAddress(&ps,   g_slot);
    cudaGetSymbolAddress(&pte,  g_tile_expert);
    cudaGetSymbolAddress(&pd,   g_done);

    cudaFuncSetAttribute(gemm_split_f16_kernel,
                         cudaFuncAttributeMaxDynamicSharedMemorySize, SPLIT_SMEM_BYTES);
    cudaFuncSetAttribute(gemm_f16_kernel<true,  1, true,  true>,
                         cudaFuncAttributeMaxDynamicSharedMemorySize, GEMM_SMEM_BYTES);
    cudaFuncSetAttribute(gemm_f16_kernel<false, 2, false, true>,
                         cudaFuncAttributeMaxDynamicSharedMemorySize, GEMM_SMEM_BYTES);

    // 0) prep: init + fp16 conversions; zero the output for fused atomic combine
    long nprep4 = (W1E + W2E + XE + WR1E) / 4;
    prep_kernel<<<(unsigned)((nprep4 + 255) / 256), 256>>>(
        (const float4*)W1, (const float4*)W2, (const float4*)x, (const float4*)Wr1,
        (__half*)pW1h, (__half*)pW2h, (__half*)pxh, (__half*)pxl,
        (__half*)pwh, (__half*)pwl,
        (int*)pp, (int*)pc, (int*)pd);
    cudaMemsetAsync(out, 0, (size_t)out_size * sizeof(float));

    // 1) router hidden: H1 = GELU(x @ Wr1 + br1), fp16 split (near-fp32)
    gemm_split_f16_kernel<<<dim3(D_DIM / BN, T_TOK / BM), 256, SPLIT_SMEM_BYTES>>>(
        (const __half*)pxh, (const __half*)pxl, (const __half*)pwh, (const __half*)pwl,
        br1, (float*)pH1, D_DIM, D_DIM);

    // 2) logits + softmax + top-2 + counts + scan + fill (+ per-slot weights)
    route_kernel<<<T_TOK / 8, 256>>>((const float*)pH1, Wr2, br2,
                                     (int*)pti, (float*)ptw, (int*)pc, (int*)pd,
                                     (int*)pp, (int*)ps, (float*)pws, (int*)pte);

    // 3) expert layer 1 (grouped, gathered): h = fp16(GELU(xh[perm] @ W1h + b1))
    gemm_f16_kernel<true, 1, true, true>
        <<<dim3(H_DIM / BN, MTILES), 256, GEMM_SMEM_BYTES>>>(
            (const __half*)pxh, (const __half*)pW1h, b1, ph, H_DIM, D_DIM,
            (const int*)pp, (const int*)pte, (long)D_DIM * H_DIM, H_DIM, nullptr);

    // 4) expert layer 2 + fused weighted combine:
    //    out[token] += wslot[slot] * (h[slot] @ W2h + b2)   (2 addends/element, order-invariant)
    gemm_f16_kernel<false, 2, false, true>
        <<<dim3(D_DIM / BN, MTILES), 256, GEMM_SMEM_BYTES>>>(
            (const __half*)ph, (const __half*)pW2h, b2, out, D_DIM, H_DIM,
            (const int*)pp, (const int*)pte, (long)H_DIM * D_DIM, D_DIM,
            (const float*)pws);
}

// round 12
// speedup vs baseline: 2.0338x; 1.0158x over previous
#include <cuda_runtime.h>
#include <cuda_fp16.h>
#include <cstdint>
#include <cmath>

// ---------------- problem constants ----------------
#define T_TOK  8192
#define D_DIM  1024
#define E_EXP  8
#define H_DIM  4096
#define MPAD   17408
#define MTILES 136

#define XE   8388608L
#define WR1E 1048576L
#define W1E  33554432L
#define W2E  33554432L

// ---------------- scratch ----------------
__device__ float  g_H1[(size_t)T_TOK * D_DIM];   // router hidden (fp32)
__device__ __half g_h [(size_t)MPAD * H_DIM];    // expert hidden (fp16)
__device__ __half g_W1h[W1E];                    // fp16(W1) [E][D][H]
__device__ __half g_W2h[W2E];                    // fp16(W2) [E][H][D]
__device__ __half g_xh[XE];
__device__ __half g_xl[XE];
__device__ __half g_wh[WR1E];
__device__ __half g_wl[WR1E];
__device__ int    g_topk_idx[T_TOK * 2];
__device__ float  g_topk_w [T_TOK * 2];
__device__ float  g_wslot  [MPAD];               // per-slot combine weight
__device__ int    g_counts [E_EXP];
__device__ int    g_perm   [MPAD];
__device__ int    g_slot   [T_TOK * 2];
__device__ int    g_tile_expert[MTILES];
__device__ int    g_done;

// ---------------- helpers ----------------
__device__ __forceinline__ float gelu_exact(float x) {
    return 0.5f * x * (1.0f + erff(x * 0.70710678118654752440f));
}
__device__ __forceinline__ void mma_f16(float c[4],
                                        uint32_t a0, uint32_t a1, uint32_t a2, uint32_t a3,
                                        uint32_t b0, uint32_t b1) {
    asm volatile(
        "mma.sync.aligned.m16n8k16.row.col.f32.f16.f16.f32 "
        "{%0,%1,%2,%3}, {%4,%5,%6,%7}, {%8,%9}, {%0,%1,%2,%3};\n"
        : "+f"(c[0]), "+f"(c[1]), "+f"(c[2]), "+f"(c[3])
        : "r"(a0), "r"(a1), "r"(a2), "r"(a3), "r"(b0), "r"(b1));
}
__device__ __forceinline__ void ldsm_x4(uint32_t& r0, uint32_t& r1, uint32_t& r2, uint32_t& r3,
                                        uint32_t addr) {
    asm volatile("ldmatrix.sync.aligned.m8n8.x4.shared.b16 {%0,%1,%2,%3}, [%4];"
                 : "=r"(r0), "=r"(r1), "=r"(r2), "=r"(r3) : "r"(addr));
}
__device__ __forceinline__ void ldsm_x4_t(uint32_t& r0, uint32_t& r1, uint32_t& r2, uint32_t& r3,
                                          uint32_t addr) {
    asm volatile("ldmatrix.sync.aligned.m8n8.x4.trans.shared.b16 {%0,%1,%2,%3}, [%4];"
                 : "=r"(r0), "=r"(r1), "=r"(r2), "=r"(r3) : "r"(addr));
}
__device__ __forceinline__ void cp_async16(void* smem_dst, const void* gmem_src, unsigned src_bytes) {
    unsigned d = (unsigned)__cvta_generic_to_shared(smem_dst);
    asm volatile("cp.async.ca.shared.global [%0], [%1], 16, %2;\n"
                 :: "r"(d), "l"(gmem_src), "r"(src_bytes) : "memory");
}
__device__ __forceinline__ void cp_async16_ca(uint32_t smem_dst, const void* gmem_src) {
    asm volatile("cp.async.ca.shared.global [%0], [%1], 16;\n"
                 :: "r"(smem_dst), "l"(gmem_src) : "memory");
}
__device__ __forceinline__ void cp_async16_cg(uint32_t smem_dst, const void* gmem_src) {
    asm volatile("cp.async.cg.shared.global [%0], [%1], 16;\n"
                 :: "r"(smem_dst), "l"(gmem_src) : "memory");
}
__device__ __forceinline__ uint32_t smem_u32(const void* p) {
    return (uint32_t)__cvta_generic_to_shared(p);
}
__device__ __forceinline__ void red_add_v2(float* addr, float v0, float v1) {
    asm volatile("red.global.add.v2.f32 [%0], {%1, %2};"
                 :: "l"(addr), "f"(v0), "f"(v1) : "memory");
}

// ---------------- main GEMM tiling (BK=32, 4-stage, 2 barriers/slice) -------
constexpr int BM = 128, BN = 128, BK = 32;      // BK in halves
constexpr int NSTG = 4;
constexpr int AS = 40;                          // A smem stride (halves), LDSM conflict-free
constexpr int BS = 136;                         // B smem stride (halves), LDSM conflict-free
constexpr int A_HELE = BM * AS;                 // 5120
constexpr int B_HELE = BK * BS;                 // 4352
constexpr int GEMM_SMEM_BYTES = NSTG * (A_HELE + B_HELE) * 2;    // 75776

// OUT_MODE: 0 = fp32 store, 1 = fp16 store, 2 = fused weighted atomic combine
template<bool DO_GELU, int OUT_MODE, bool GATHER, bool EXPERT>
__global__ __launch_bounds__(256, 2)
void gemm_f16_kernel(const __half* __restrict__ A,
                     const __half* __restrict__ Bbase,
                     const float* __restrict__ biasBase,
                     void* __restrict__ Cv,
                     int N, int Kdim,
                     const int* __restrict__ perm,
                     const int* __restrict__ tile_expert,
                     long strideB, int strideBias,
                     const float* __restrict__ wslot)
{
    extern __shared__ __half smem[];
    __half* As = smem;                          // [NSTG][A_HELE]
    __half* Bs = smem + NSTG * A_HELE;          // [NSTG][B_HELE]

    const int mtile = blockIdx.y;
    const int ntile = blockIdx.x;

    const __half* Bp  = Bbase;
    const float* bias = biasBase;
    if (EXPERT) {
        int e = tile_expert[mtile];
        if (e < 0) return;
        Bp   += (long)e * strideB;
        bias += (long)e * strideBias;
    }

    const int tid   = threadIdx.x;
    const int lane  = tid & 31;
    const int warp  = tid >> 5;
    const int warpM = warp & 1;                 // 0..1 (64 rows each)
    const int warpN = warp >> 1;                // 0..3 (32 cols each)
    const int mbase = mtile * BM;
    const int nbase = ntile * BN;

    float acc[4][4][4];
    #pragma unroll
    for (int mi = 0; mi < 4; mi++)
        #pragma unroll
        for (int ni = 0; ni < 4; ni++)
            #pragma unroll
            for (int r = 0; r < 4; r++) acc[mi][ni][r] = 0.0f;

    const int KT = Kdim / BK;                   // multiple of 4 here (32 or 128)

    // ---- hoisted load state ----
    const __half* aptr[2];
    uint32_t adst[2];
    #pragma unroll
    for (int i = 0; i < 2; i++) {
        int c = tid + i * 256;
        int r = c >> 2;
        int off = (c & 3) * 8;
        adst[i] = smem_u32(&As[r * AS + off]);
        if (GATHER) {
            int g = perm[mbase + r];
            if (g < 0) g = 0;                   // pad rows: any valid row (output discarded)
            aptr[i] = A + (long)g * Kdim + off;
        } else {
            aptr[i] = A + (long)(mbase + r) * Kdim + off;
        }
    }
    const __half* bptr[2];
    uint32_t bdst[2];
    #pragma unroll
    for (int i = 0; i < 2; i++) {
        int c = tid + i * 256;
        int r = c >> 4;
        int off = (c & 15) * 8;
        bdst[i] = smem_u32(&Bs[r * BS + off]);
        bptr[i] = Bp + (long)r * N + nbase + off;
    }
    const long bstep = (long)BK * N;

    auto load_tiles = [&](int stage) {
        const uint32_t soA = stage * (A_HELE * 2);
        const uint32_t soB = stage * (B_HELE * 2);
        #pragma unroll
        for (int i = 0; i < 2; i++) {
            cp_async16_ca(adst[i] + soA, aptr[i]);
            aptr[i] += BK;
        }
        #pragma unroll
        for (int i = 0; i < 2; i++) {
            cp_async16_cg(bdst[i] + soB, bptr[i]);
            bptr[i] += bstep;
        }
        asm volatile("cp.async.commit_group;\n" ::: "memory");
    };

    const uint32_t as_u = smem_u32(As);
    const uint32_t bs_u = smem_u32(Bs);
    const int tl = lane >> 3;
    const int lr = lane & 7;
    const int a_row0 = warpM * 64 + (tl & 1) * 8 + lr;
    const int a_col0 = (tl >> 1) * 8;
    const int b_krow0 = (tl & 1) * 8 + lr;
    const int b_col0  = warpN * 32 + (tl >> 1) * 8;

    auto compute_stage = [&](int stage) {
        const uint32_t asu = as_u + stage * (A_HELE * 2);
        const uint32_t bsu = bs_u + stage * (B_HELE * 2);
        #pragma unroll
        for (int ks = 0; ks < 2; ks++) {
            uint32_t a[4][4];
            #pragma unroll
            for (int mi = 0; mi < 4; mi++)
                ldsm_x4(a[mi][0], a[mi][1], a[mi][2], a[mi][3],
                        asu + ((a_row0 + mi * 16) * AS + ks * 16 + a_col0) * 2);
            uint32_t b[4][2];
            #pragma unroll
            for (int nj = 0; nj < 2; nj++)
                ldsm_x4_t(b[2 * nj][0], b[2 * nj][1], b[2 * nj + 1][0], b[2 * nj + 1][1],
                          bsu + ((b_krow0 + ks * 16) * BS + b_col0 + nj * 16) * 2);
            #pragma unroll
            for (int mi = 0; mi < 4; mi++)
                #pragma unroll
                for (int ni = 0; ni < 4; ni++)
                    mma_f16(acc[mi][ni], a[mi][0], a[mi][1], a[mi][2], a[mi][3],
                            b[ni][0], b[ni][1]);
        }
    };

    load_tiles(0);
    load_tiles(1);
    load_tiles(2);

    for (int kt = 0; kt < KT; kt += 4) {
        #pragma unroll
        for (int u = 0; u < 4; u++) {
            const int k = kt + u;
            const int p = (KT - k) < 3 ? (KT - k) : 3;
            if (p == 3)      asm volatile("cp.async.wait_group 2;\n" ::: "memory");
            else if (p == 2) asm volatile("cp.async.wait_group 1;\n" ::: "memory");
            else             asm volatile("cp.async.wait_group 0;\n" ::: "memory");
            __syncthreads();
            compute_stage(u);
            __syncthreads();
            if (k + 3 < KT) load_tiles((u + 3) & 3);
        }
    }

    // epilogue
    #pragma unroll
    for (int mi = 0; mi < 4; mi++) {
        const int r0 = mbase + warpM * 64 + mi * 16 + (lane >> 2);
        const int r1 = r0 + 8;
        int   g0 = 0, g1 = 0;
        float w0 = 0.0f, w1 = 0.0f;
        if (OUT_MODE == 2) {
            g0 = perm[r0]; g1 = perm[r1];
            w0 = wslot[r0]; w1 = wslot[r1];
        }
        #pragma unroll
        for (int ni = 0; ni < 4; ni++) {
            int col0 = nbase + warpN * 32 + ni * 8 + (lane & 3) * 2;
            float bv0 = bias[col0], bv1 = bias[col0 + 1];
            float v00 = acc[mi][ni][0] + bv0;
            float v01 = acc[mi][ni][1] + bv1;
            float v10 = acc[mi][ni][2] + bv0;
            float v11 = acc[mi][ni][3] + bv1;
            if (DO_GELU) {
                v00 = gelu_exact(v00); v01 = gelu_exact(v01);
                v10 = gelu_exact(v10); v11 = gelu_exact(v11);
            }
            if (OUT_MODE == 1) {
                __half* C = (__half*)Cv;
                *reinterpret_cast<__half2*>(C + (long)r0 * N + col0) = __floats2half2_rn(v00, v01);
                *reinterpret_cast<__half2*>(C + (long)r1 * N + col0) = __floats2half2_rn(v10, v11);
            } else if (OUT_MODE == 0) {
                float* C = (float*)Cv;
                *reinterpret_cast<float2*>(C + (long)r0 * N + col0) = make_float2(v00, v01);
                *reinterpret_cast<float2*>(C + (long)r1 * N + col0) = make_float2(v10, v11);
            } else {
                // fused weighted combine: out[token, col] += w * v (vector red)
                float* O = (float*)Cv;
                if (g0 >= 0) red_add_v2(&O[(long)g0 * N + col0], w0 * v00, w0 * v01);
                if (g1 >= 0) red_add_v2(&O[(long)g1 * N + col0], w1 * v10, w1 * v11);
            }
        }
    }
}

// ---------------- router GEMM: fp16 hi/lo split + fused W1/W2 converters ----
constexpr int RAS = 40;
constexpr int RBS = 136;
constexpr int RA_HELE = BM * RAS;
constexpr int RB_HELE = BK * RBS;
constexpr int SPLIT_SMEM_BYTES = (4 * RA_HELE + 4 * RB_HELE) * 2;
constexpr int SPLIT_YT = T_TOK / BM;            // 64 real m-tiles
constexpr int CONV_Y   = 24;                    // extra block rows for W conversion
constexpr long CONV_THREADS = (long)CONV_Y * 8 * 256;   // 49152

__global__ __launch_bounds__(256, 2)
void gemm_split_f16_kernel(const __half* __restrict__ Ahi, const __half* __restrict__ Alo,
                           const __half* __restrict__ Bhi, const __half* __restrict__ Blo,
                           const float* __restrict__ bias,
                           float* __restrict__ C, int N, int Kdim,
                           const float4* __restrict__ W1, const float4* __restrict__ W2,
                           __half* __restrict__ W1h, __half* __restrict__ W2h)
{
    const int mtile = blockIdx.y;
    // ---- converter blocks: fp32 W1/W2 -> fp16, overlapped with tensor blocks
    if (mtile >= SPLIT_YT) {
        long cb = (long)(mtile - SPLIT_YT) * gridDim.x + blockIdx.x;
        const long total = (W1E + W2E) / 4;
        for (long i = cb * 256 + threadIdx.x; i < total; i += CONV_THREADS) {
            if (i < W1E / 4) {
                float4 v = W1[i];
                __half2* p = reinterpret_cast<__half2*>(W1h + i * 4);
                p[0] = __floats2half2_rn(v.x, v.y);
                p[1] = __floats2half2_rn(v.z, v.w);
            } else {
                long j = i - W1E / 4;
                float4 v = W2[j];
                __half2* p = reinterpret_cast<__half2*>(W2h + j * 4);
                p[0] = __floats2half2_rn(v.x, v.y);
                p[1] = __floats2half2_rn(v.z, v.w);
            }
        }
        return;
    }

    extern __shared__ __half hsmem[];
    __half* AsH = hsmem;
    __half* AsL = AsH + 2 * RA_HELE;
    __half* BsH = AsL + 2 * RA_HELE;
    __half* BsL = BsH + 2 * RB_HELE;

    const int ntile = blockIdx.x;
    const int tid   = threadIdx.x;
    const int lane  = tid & 31;
    const int warp  = tid >> 5;
    const int warpM = warp & 1;
    const int warpN = warp >> 1;
    const int mbase = mtile * BM;
    const int nbase = ntile * BN;

    float acc[4][4][4];
    #pragma unroll
    for (int mi = 0; mi < 4; mi++)
        #pragma unroll
        for (int ni = 0; ni < 4; ni++)
            #pragma unroll
            for (int r = 0; r < 4; r++) acc[mi][ni][r] = 0.0f;

    const int KT = Kdim / BK;

    auto load_tiles = [&](int kt, int stage) {
        const int k0 = kt * BK;
        #pragma unroll
        for (int i = 0; i < 2; i++) {
            int c   = tid + i * 256;
            int r   = c >> 2;
            int off = (c & 3) * 8;
            long go = (long)(mbase + r) * Kdim + k0 + off;
            cp_async16(&AsH[stage * RA_HELE + r * RAS + off], Ahi + go, 16);
            cp_async16(&AsL[stage * RA_HELE + r * RAS + off], Alo + go, 16);
        }
        #pragma unroll
        for (int i = 0; i < 2; i++) {
            int c   = tid + i * 256;
            int r   = c >> 4;
            int off = (c & 15) * 8;
            long go = (long)(k0 + r) * N + nbase + off;
            cp_async16(&BsH[stage * RB_HELE + r * RBS + off], Bhi + go, 16);
            cp_async16(&BsL[stage * RB_HELE + r * RBS + off], Blo + go, 16);
        }
        asm volatile("cp.async.commit_group;\n" ::: "memory");
    };

    const uint32_t ash_u = smem_u32(AsH);
    const uint32_t asl_u = smem_u32(AsL);
    const uint32_t bsh_u = smem_u32(BsH);
    const uint32_t bsl_u = smem_u32(BsL);
    const int tl = lane >> 3;
    const int lr = lane & 7;
    const int a_row0 = warpM * 64 + (tl & 1) * 8 + lr;
    const int a_col0 = (tl >> 1) * 8;
    const int b_krow0 = (tl & 1) * 8 + lr;
    const int b_col0  = warpN * 32 + (tl >> 1) * 8;

    load_tiles(0, 0);
    for (int kt = 0; kt < KT; kt++) {
        if (kt + 1 < KT) {
            load_tiles(kt + 1, (kt + 1) & 1);
            asm volatile("cp.async.wait_group 1;\n" ::: "memory");
        } else {
            asm volatile("cp.async.wait_group 0;\n" ::: "memory");
        }
        __syncthreads();

        const uint32_t ashu = ash_u + (kt & 1) * (RA_HELE * 2);
        const uint32_t aslu = asl_u + (kt & 1) * (RA_HELE * 2);
        const uint32_t bshu = bsh_u + (kt & 1) * (RB_HELE * 2);
        const uint32_t bslu = bsl_u + (kt & 1) * (RB_HELE * 2);

        #pragma unroll
        for (int ks = 0; ks < 2; ks++) {
            uint32_t ah[4][4], al[4][4];
            #pragma unroll
            for (int mi = 0; mi < 4; mi++) {
                uint32_t off = ((a_row0 + mi * 16) * RAS + ks * 16 + a_col0) * 2;
                ldsm_x4(ah[mi][0], ah[mi][1], ah[mi][2], ah[mi][3], ashu + off);
                ldsm_x4(al[mi][0], al[mi][1], al[mi][2], al[mi][3], aslu + off);
            }
            uint32_t bh[4][2], bl[4][2];
            #pragma unroll
            for (int nj = 0; nj < 2; nj++) {
                uint32_t off = ((b_krow0 + ks * 16) * RBS + b_col0 + nj * 16) * 2;
                ldsm_x4_t(bh[2 * nj][0], bh[2 * nj][1], bh[2 * nj + 1][0], bh[2 * nj + 1][1], bshu + off);
                ldsm_x4_t(bl[2 * nj][0], bl[2 * nj][1], bl[2 * nj + 1][0], bl[2 * nj + 1][1], bslu + off);
            }
            #pragma unroll
            for (int mi = 0; mi < 4; mi++)
                #pragma unroll
                for (int ni = 0; ni < 4; ni++) {
                    mma_f16(acc[mi][ni], ah[mi][0], ah[mi][1], ah[mi][2], ah[mi][3],
                            bl[ni][0], bl[ni][1]);
                    mma_f16(acc[mi][ni], al[mi][0], al[mi][1], al[mi][2], al[mi][3],
                            bh[ni][0], bh[ni][1]);
                    mma_f16(acc[mi][ni], ah[mi][0], ah[mi][1], ah[mi][2], ah[mi][3],
                            bh[ni][0], bh[ni][1]);
                }
        }
        __syncthreads();
    }

    #pragma unroll
    for (int mi = 0; mi < 4; mi++) {
        #pragma unroll
        for (int ni = 0; ni < 4; ni++) {
            int row0 = mbase + warpM * 64 + mi * 16 + (lane >> 2);
            int col0 = nbase + warpN * 32 + ni * 8 + (lane & 3) * 2;
            float bv0 = bias[col0], bv1 = bias[col0 + 1];
            float v00 = gelu_exact(acc[mi][ni][0] + bv0);
            float v01 = gelu_exact(acc[mi][ni][1] + bv1);
            float v10 = gelu_exact(acc[mi][ni][2] + bv0);
            float v11 = gelu_exact(acc[mi][ni][3] + bv1);
            *reinterpret_cast<float2*>(&C[(long)(row0    ) * N + col0]) = make_float2(v00, v01);
            *reinterpret_cast<float2*>(&C[(long)(row0 + 8) * N + col0]) = make_float2(v10, v11);
        }
    }
}

// ---------------- prep: init + x/Wr1 fp16 splits (weights moved to router) --
__global__ void prep_kernel(const float4* __restrict__ x, const float4* __restrict__ Wr1,
                            __half* __restrict__ xh, __half* __restrict__ xl,
                            __half* __restrict__ wh, __half* __restrict__ wl,
                            int* __restrict__ perm, int* __restrict__ counts,
                            int* __restrict__ done)
{
    long i = (long)blockIdx.x * 256 + threadIdx.x;
    if (i < MPAD)  perm[i] = -1;
    if (i < E_EXP) counts[i] = 0;
    if (i == 0)    *done = 0;

    if (i < XE / 4) {
        float4 v = x[i];
        __half h0 = __float2half_rn(v.x), h1 = __float2half_rn(v.y);
        __half h2 = __float2half_rn(v.z), h3 = __float2half_rn(v.w);
        __half2* ph = reinterpret_cast<__half2*>(xh + i * 4);
        ph[0] = __halves2half2(h0, h1);
        ph[1] = __halves2half2(h2, h3);
        __half2* pl = reinterpret_cast<__half2*>(xl + i * 4);
        pl[0] = __floats2half2_rn(v.x - __half2float(h0), v.y - __half2float(h1));
        pl[1] = __floats2half2_rn(v.z - __half2float(h2), v.w - __half2float(h3));
    } else if (i < (XE + WR1E) / 4) {
        long j = i - XE / 4;
        float4 v = Wr1[j];
        __half h0 = __float2half_rn(v.x), h1 = __float2half_rn(v.y);
        __half h2 = __float2half_rn(v.z), h3 = __float2half_rn(v.w);
        __half2* ph = reinterpret_cast<__half2*>(wh + j * 4);
        ph[0] = __halves2half2(h0, h1);
        ph[1] = __halves2half2(h2, h3);
        __half2* pl = reinterpret_cast<__half2*>(wl + j * 4);
        pl[0] = __floats2half2_rn(v.x - __half2float(h0), v.y - __half2float(h1));
        pl[1] = __floats2half2_rn(v.z - __half2float(h2), v.w - __half2float(h3));
    }
}

// ---------------- route: logits + softmax + top-2 + (last block) scan/fill --
__global__ void route_kernel(const float* __restrict__ H1,
                             const float* __restrict__ Wr2,
                             const float* __restrict__ br2,
                             int*   __restrict__ topk_idx,
                             float* __restrict__ topk_w,
                             int*   __restrict__ counts,
                             int*   __restrict__ done,
                             int*   __restrict__ perm,
                             int*   __restrict__ slot,
                             float* __restrict__ wslot,
                             int*   __restrict__ tile_expert)
{
    int warp = threadIdx.x >> 5, lane = threadIdx.x & 31;
    int t = blockIdx.x * 8 + warp;
    const float* h = H1 + (long)t * D_DIM;

    float acc[E_EXP];
    #pragma unroll
    for (int e = 0; e < E_EXP; e++) acc[e] = 0.0f;

    #pragma unroll 4
    for (int i = 0; i < D_DIM / 32; i++) {
        int d = i * 32 + lane;
        float hv = h[d];
        const float4* w4 = reinterpret_cast<const float4*>(Wr2 + (long)d * E_EXP);
        float4 wa = w4[0], wb = w4[1];
        acc[0] += hv * wa.x; acc[1] += hv * wa.y; acc[2] += hv * wa.z; acc[3] += hv * wa.w;
        acc[4] += hv * wb.x; acc[5] += hv * wb.y; acc[6] += hv * wb.z; acc[7] += hv * wb.w;
    }
    #pragma unroll
    for (int e = 0; e < E_EXP; e++)
        #pragma unroll
        for (int off = 16; off; off >>= 1)
            acc[e] += __shfl_xor_sync(0xFFFFFFFFu, acc[e], off);

    if (lane == 0) {
        float l[E_EXP];
        #pragma unroll
        for (int e = 0; e < E_EXP; e++) l[e] = acc[e] + br2[e];
        int e0 = 0;
        #pragma unroll
        for (int e = 1; e < E_EXP; e++) if (l[e] > l[e0]) e0 = e;
        int e1 = -1;
        #pragma unroll
        for (int e = 0; e < E_EXP; e++)
            if (e != e0 && (e1 < 0 || l[e] > l[e1])) e1 = e;
        float m  = l[e0];
        float p0 = expf(l[e0] - m);
        float p1 = expf(l[e1] - m);
        float inv = 1.0f / (p0 + p1);
        topk_idx[t * 2]     = e0;
        topk_idx[t * 2 + 1] = e1;
        topk_w[t * 2]       = p0 * inv;
        topk_w[t * 2 + 1]   = p1 * inv;
        atomicAdd(&counts[e0], 1);
        atomicAdd(&counts[e1], 1);
    }

    __syncthreads();
    __shared__ int is_last;
    if (threadIdx.x == 0) {
        __threadfence();
        int prev = atomicAdd(done, 1);
        is_last = (prev == (int)gridDim.x - 1);
    }
    __syncthreads();
    if (!is_last) return;
    __threadfence();

    __shared__ int s_off[E_EXP + 1];
    __shared__ int s_fill[E_EXP];
    if (threadIdx.x == 0) {
        int off = 0;
        for (int e = 0; e < E_EXP; e++) {
            s_off[e] = off;
            off += (counts[e] + 127) & ~127;
        }
        s_off[E_EXP] = off;
        int e = 0;
        for (int tile = 0; tile < MTILES; tile++) {
            int r = tile * 128;
            if (r >= off) { tile_expert[tile] = -1; continue; }
            while (e < E_EXP && r >= s_off[e + 1]) e++;
            tile_expert[tile] = e;
        }
    }
    if (threadIdx.x < E_EXP) s_fill[threadIdx.x] = 0;
    __syncthreads();

    for (int tt = threadIdx.x; tt < T_TOK; tt += 256) {
        #pragma unroll
        for (int k = 0; k < 2; k++) {
            int e   = topk_idx[tt * 2 + k];
            int pos = s_off[e] + atomicAdd(&s_fill[e], 1);
            perm[pos]        = tt;
            slot[tt * 2 + k] = pos;
            wslot[pos]       = topk_w[tt * 2 + k];
        }
    }
}

// ---------------- launch ----------------
extern "C" void kernel_launch(void* const* d_in, const int* in_sizes, int n_in,
                              void* d_out, int out_size)
{
    const float* x   = (const float*)d_in[0];
    const float* Wr1 = (const float*)d_in[1];
    const float* br1 = (const float*)d_in[2];
    const float* Wr2 = (const float*)d_in[3];
    const float* br2 = (const float*)d_in[4];
    const float* W1  = (const float*)d_in[5];
    const float* b1  = (const float*)d_in[6];
    const float* W2  = (const float*)d_in[7];
    const float* b2  = (const float*)d_in[8];
    float* out = (float*)d_out;

    void *pH1, *ph, *pW1h, *pW2h, *pxh, *pxl, *pwh, *pwl;
    void *pti, *ptw, *pws, *pc, *pp, *ps, *pte, *pd;
    cudaGetSymbolAddress(&pH1,  g_H1);
    cudaGetSymbolAddress(&ph,   g_h);
    cudaGetSymbolAddress(&pW1h, g_W1h);
    cudaGetSymbolAddress(&pW2h, g_W2h);
    cudaGetSymbolAddress(&pxh,  g_xh);
    cudaGetSymbolAddress(&pxl,  g_xl);
    cudaGetSymbolAddress(&pwh,  g_wh);
    cudaGetSymbolAddress(&pwl,  g_wl);
    cudaGetSymbolAddress(&pti,  g_topk_idx);
    cudaGetSymbolAddress(&ptw,  g_topk_w);
    cudaGetSymbolAddress(&pws,  g_wslot);
    cudaGetSymbolAddress(&pc,   g_counts);
    cudaGetSymbolAddress(&pp,   g_perm);
    cudaGetSymbolAddress(&ps,   g_slot);
    cudaGetSymbolAddress(&pte,  g_tile_expert);
    cudaGetSymbolAddress(&pd,   g_done);

    cudaFuncSetAttribute(gemm_split_f16_kernel,
                         cudaFuncAttributeMaxDynamicSharedMemorySize, SPLIT_SMEM_BYTES);
    cudaFuncSetAttribute(gemm_f16_kernel<true,  1, true,  true>,
                         cudaFuncAttributeMaxDynamicSharedMemorySize, GEMM_SMEM_BYTES);
    cudaFuncSetAttribute(gemm_f16_kernel<false, 2, false, true>,
                         cudaFuncAttributeMaxDynamicSharedMemorySize, GEMM_SMEM_BYTES);

    // 0) prep: init + x/Wr1 fp16 splits; zero the output for fused atomic combine
    long nprep4 = (XE + WR1E) / 4;
    prep_kernel<<<(unsigned)((nprep4 + 255) / 256), 256>>>(
        (const float4*)x, (const float4*)Wr1,
        (__half*)pxh, (__half*)pxl, (__half*)pwh, (__half*)pwl,
        (int*)pp, (int*)pc, (int*)pd);
    cudaMemsetAsync(out, 0, (size_t)out_size * sizeof(float));

    // 1) router hidden: H1 = GELU(x @ Wr1 + br1), fp16 split (near-fp32),
    //    + 192 fused converter blocks turning W1/W2 into fp16 in the scheduling tail
    gemm_split_f16_kernel<<<dim3(D_DIM / BN, SPLIT_YT + CONV_Y), 256, SPLIT_SMEM_BYTES>>>(
        (const __half*)pxh, (const __half*)pxl, (const __half*)pwh, (const __half*)pwl,
        br1, (float*)pH1, D_DIM, D_DIM,
        (const float4*)W1, (const float4*)W2, (__half*)pW1h, (__half*)pW2h);

    // 2) logits + softmax + top-2 + counts + scan + fill (+ per-slot weights)
    route_kernel<<<T_TOK / 8, 256>>>((const float*)pH1, Wr2, br2,
                                     (int*)pti, (float*)ptw, (int*)pc, (int*)pd,
                                     (int*)pp, (int*)ps, (float*)pws, (int*)pte);

    // 3) expert layer 1 (grouped, gathered): h = fp16(GELU(xh[perm] @ W1h + b1))
    gemm_f16_kernel<true, 1, true, true>
        <<<dim3(H_DIM / BN, MTILES), 256, GEMM_SMEM_BYTES>>>(
            (const __half*)pxh, (const __half*)pW1h, b1, ph, H_DIM, D_DIM,
            (const int*)pp, (const int*)pte, (long)D_DIM * H_DIM, H_DIM, nullptr);

    // 4) expert layer 2 + fused weighted combine (red.v2, 2 addends/element):
    gemm_f16_kernel<false, 2, false, true>
        <<<dim3(D_DIM / BN, MTILES), 256, GEMM_SMEM_BYTES>>>(
            (const __half*)ph, (const __half*)pW2h, b2, out, D_DIM, H_DIM,
            (const int*)pp, (const int*)pte, (long)H_DIM * D_DIM, D_DIM,
            (const float*)pws);
}

// round 14
// speedup vs baseline: 2.0453x; 1.0056x over previous
#include <cuda_runtime.h>
#include <cuda_fp16.h>
#include <cstdint>
#include <cmath>

// ---------------- problem constants ----------------
#define T_TOK  8192
#define D_DIM  1024
#define E_EXP  8
#define H_DIM  4096
#define MPAD   17408
#define MTILES 136

#define XE   8388608L
#define WR1E 1048576L
#define W1E  33554432L
#define W2E  33554432L

#define OUT4 ((long)T_TOK * D_DIM / 4)

// ---------------- scratch ----------------
__device__ float  g_H1[(size_t)T_TOK * D_DIM];   // router hidden (fp32)
__device__ __half g_h [(size_t)MPAD * H_DIM];    // expert hidden (fp16)
__device__ __half g_W1h[W1E];                    // fp16(W1) [E][D][H]
__device__ __half g_W2h[W2E];                    // fp16(W2) [E][H][D]
__device__ __half g_xh[XE];
__device__ __half g_xl[XE];
__device__ __half g_wh[WR1E];
__device__ __half g_wl[WR1E];
__device__ int    g_topk_idx[T_TOK * 2];
__device__ float  g_topk_w [T_TOK * 2];
__device__ float  g_wslot  [MPAD];               // per-slot combine weight
__device__ int    g_counts [E_EXP];
__device__ int    g_perm   [MPAD];
__device__ int    g_slot   [T_TOK * 2];
__device__ int    g_tile_expert[MTILES];
__device__ int    g_done;
__device__ int    g_done1  [MTILES];             // layer-1 completion counters

// ---------------- helpers ----------------
__device__ __forceinline__ float gelu_exact(float x) {
    return 0.5f * x * (1.0f + erff(x * 0.70710678118654752440f));
}
__device__ __forceinline__ void mma_f16(float c[4],
                                        uint32_t a0, uint32_t a1, uint32_t a2, uint32_t a3,
                                        uint32_t b0, uint32_t b1) {
    asm volatile(
        "mma.sync.aligned.m16n8k16.row.col.f32.f16.f16.f32 "
        "{%0,%1,%2,%3}, {%4,%5,%6,%7}, {%8,%9}, {%0,%1,%2,%3};\n"
        : "+f"(c[0]), "+f"(c[1]), "+f"(c[2]), "+f"(c[3])
        : "r"(a0), "r"(a1), "r"(a2), "r"(a3), "r"(b0), "r"(b1));
}
__device__ __forceinline__ void ldsm_x4(uint32_t& r0, uint32_t& r1, uint32_t& r2, uint32_t& r3,
                                        uint32_t addr) {
    asm volatile("ldmatrix.sync.aligned.m8n8.x4.shared.b16 {%0,%1,%2,%3}, [%4];"
                 : "=r"(r0), "=r"(r1), "=r"(r2), "=r"(r3) : "r"(addr));
}
__device__ __forceinline__ void ldsm_x4_t(uint32_t& r0, uint32_t& r1, uint32_t& r2, uint32_t& r3,
                                          uint32_t addr) {
    asm volatile("ldmatrix.sync.aligned.m8n8.x4.trans.shared.b16 {%0,%1,%2,%3}, [%4];"
                 : "=r"(r0), "=r"(r1), "=r"(r2), "=r"(r3) : "r"(addr));
}
__device__ __forceinline__ void cp_async16(void* smem_dst, const void* gmem_src, unsigned src_bytes) {
    unsigned d = (unsigned)__cvta_generic_to_shared(smem_dst);
    asm volatile("cp.async.ca.shared.global [%0], [%1], 16, %2;\n"
                 :: "r"(d), "l"(gmem_src), "r"(src_bytes) : "memory");
}
__device__ __forceinline__ void cp_async16_ca(uint32_t smem_dst, const void* gmem_src) {
    asm volatile("cp.async.ca.shared.global [%0], [%1], 16;\n"
                 :: "r"(smem_dst), "l"(gmem_src) : "memory");
}
__device__ __forceinline__ void cp_async16_cg(uint32_t smem_dst, const void* gmem_src) {
    asm volatile("cp.async.cg.shared.global [%0], [%1], 16;\n"
                 :: "r"(smem_dst), "l"(gmem_src) : "memory");
}
__device__ __forceinline__ uint32_t smem_u32(const void* p) {
    return (uint32_t)__cvta_generic_to_shared(p);
}
__device__ __forceinline__ void red_add_v2(float* addr, float v0, float v1) {
    asm volatile("red.global.add.v2.f32 [%0], {%1, %2};"
                 :: "l"(addr), "f"(v0), "f"(v1) : "memory");
}

// ---------------- main GEMM tiling (BK=32, 4-stage, 2 barriers/slice) -------
constexpr int BM = 128, BN = 128, BK = 32;      // BK in halves
constexpr int NSTG = 4;
constexpr int AS = 40;                          // A smem stride (halves), LDSM conflict-free
constexpr int BS = 136;                         // B smem stride (halves), LDSM conflict-free
constexpr int A_HELE = BM * AS;                 // 5120
constexpr int B_HELE = BK * BS;                 // 4352
constexpr int GEMM_SMEM_BYTES = NSTG * (A_HELE + B_HELE) * 2;    // 75776

constexpr int G1_NT = H_DIM / BN;               // 32 ntiles, layer 1
constexpr int G2_NT = D_DIM / BN;               // 8 ntiles, layer 2
constexpr int G1_BLOCKS = G1_NT * MTILES;       // 4352
constexpr int G2_BLOCKS = G2_NT * MTILES;       // 1088

// ---- GEMM tile body (shared by both expert layers) ----
// OUT_MODE: 1 = fp16 store, 2 = fused weighted atomic combine
template<bool DO_GELU, int OUT_MODE, bool GATHER>
__device__ __forceinline__ void gemm_body(
    int mtile, int ntile,
    const __half* __restrict__ A,
    const __half* __restrict__ Bp,
    const float*  __restrict__ bias,
    void* __restrict__ Cv,
    int N, int Kdim,
    const int* __restrict__ perm,
    const float* __restrict__ wslot,
    __half* smem)
{
    __half* As = smem;                          // [NSTG][A_HELE]
    __half* Bs = smem + NSTG * A_HELE;          // [NSTG][B_HELE]

    const int tid   = threadIdx.x;
    const int lane  = tid & 31;
    const int warp  = tid >> 5;
    const int warpM = warp & 1;
    const int warpN = warp >> 1;
    const int mbase = mtile * BM;
    const int nbase = ntile * BN;

    float acc[4][4][4];
    #pragma unroll
    for (int mi = 0; mi < 4; mi++)
        #pragma unroll
        for (int ni = 0; ni < 4; ni++)
            #pragma unroll
            for (int r = 0; r < 4; r++) acc[mi][ni][r] = 0.0f;

    const int KT = Kdim / BK;                   // multiple of 4 (32 or 128)

    const __half* aptr[2];
    uint32_t adst[2];
    #pragma unroll
    for (int i = 0; i < 2; i++) {
        int c = tid + i * 256;
        int r = c >> 2;
        int off = (c & 3) * 8;
        adst[i] = smem_u32(&As[r * AS + off]);
        if (GATHER) {
            int g = perm[mbase + r];
            if (g < 0) g = 0;                   // pad rows: output discarded
            aptr[i] = A + (long)g * Kdim + off;
        } else {
            aptr[i] = A + (long)(mbase + r) * Kdim + off;
        }
    }
    const __half* bptr[2];
    uint32_t bdst[2];
    #pragma unroll
    for (int i = 0; i < 2; i++) {
        int c = tid + i * 256;
        int r = c >> 4;
        int off = (c & 15) * 8;
        bdst[i] = smem_u32(&Bs[r * BS + off]);
        bptr[i] = Bp + (long)r * N + nbase + off;
    }
    const long bstep = (long)BK * N;

    auto load_tiles = [&](int stage) {
        const uint32_t soA = stage * (A_HELE * 2);
        const uint32_t soB = stage * (B_HELE * 2);
        #pragma unroll
        for (int i = 0; i < 2; i++) {
            cp_async16_ca(adst[i] + soA, aptr[i]);
            aptr[i] += BK;
        }
        #pragma unroll
        for (int i = 0; i < 2; i++) {
            cp_async16_cg(bdst[i] + soB, bptr[i]);
            bptr[i] += bstep;
        }
        asm volatile("cp.async.commit_group;\n" ::: "memory");
    };

    const uint32_t as_u = smem_u32(As);
    const uint32_t bs_u = smem_u32(Bs);
    const int tl = lane >> 3;
    const int lr = lane & 7;
    const int a_row0 = warpM * 64 + (tl & 1) * 8 + lr;
    const int a_col0 = (tl >> 1) * 8;
    const int b_krow0 = (tl & 1) * 8 + lr;
    const int b_col0  = warpN * 32 + (tl >> 1) * 8;

    auto compute_stage = [&](int stage) {
        const uint32_t asu = as_u + stage * (A_HELE * 2);
        const uint32_t bsu = bs_u + stage * (B_HELE * 2);
        #pragma unroll
        for (int ks = 0; ks < 2; ks++) {
            uint32_t a[4][4];
            #pragma unroll
            for (int mi = 0; mi < 4; mi++)
                ldsm_x4(a[mi][0], a[mi][1], a[mi][2], a[mi][3],
                        asu + ((a_row0 + mi * 16) * AS + ks * 16 + a_col0) * 2);
            uint32_t b[4][2];
            #pragma unroll
            for (int nj = 0; nj < 2; nj++)
                ldsm_x4_t(b[2 * nj][0], b[2 * nj][1], b[2 * nj + 1][0], b[2 * nj + 1][1],
                          bsu + ((b_krow0 + ks * 16) * BS + b_col0 + nj * 16) * 2);
            #pragma unroll
            for (int mi = 0; mi < 4; mi++)
                #pragma unroll
                for (int ni = 0; ni < 4; ni++)
                    mma_f16(acc[mi][ni], a[mi][0], a[mi][1], a[mi][2], a[mi][3],
                            b[ni][0], b[ni][1]);
        }
    };

    load_tiles(0);
    load_tiles(1);
    load_tiles(2);

    for (int kt = 0; kt < KT; kt += 4) {
        #pragma unroll
        for (int u = 0; u < 4; u++) {
            const int k = kt + u;
            const int p = (KT - k) < 3 ? (KT - k) : 3;
            if (p == 3)      asm volatile("cp.async.wait_group 2;\n" ::: "memory");
            else if (p == 2) asm volatile("cp.async.wait_group 1;\n" ::: "memory");
            else             asm volatile("cp.async.wait_group 0;\n" ::: "memory");
            __syncthreads();
            compute_stage(u);
            __syncthreads();
            if (k + 3 < KT) load_tiles((u + 3) & 3);
        }
    }

    // epilogue
    #pragma unroll
    for (int mi = 0; mi < 4; mi++) {
        const int r0 = mbase + warpM * 64 + mi * 16 + (lane >> 2);
        const int r1 = r0 + 8;
        int   g0 = 0, g1 = 0;
        float w0 = 0.0f, w1 = 0.0f;
        if (OUT_MODE == 2) {
            g0 = perm[r0]; g1 = perm[r1];
            w0 = wslot[r0]; w1 = wslot[r1];
        }
        #pragma unroll
        for (int ni = 0; ni < 4; ni++) {
            int col0 = nbase + warpN * 32 + ni * 8 + (lane & 3) * 2;
            float bv0 = bias[col0], bv1 = bias[col0 + 1];
            float v00 = acc[mi][ni][0] + bv0;
            float v01 = acc[mi][ni][1] + bv1;
            float v10 = acc[mi][ni][2] + bv0;
            float v11 = acc[mi][ni][3] + bv1;
            if (DO_GELU) {
                v00 = gelu_exact(v00); v01 = gelu_exact(v01);
                v10 = gelu_exact(v10); v11 = gelu_exact(v11);
            }
            if (OUT_MODE == 1) {
                __half* C = (__half*)Cv;
                *reinterpret_cast<__half2*>(C + (long)r0 * N + col0) = __floats2half2_rn(v00, v01);
                *reinterpret_cast<__half2*>(C + (long)r1 * N + col0) = __floats2half2_rn(v10, v11);
            } else {
                float* O = (float*)Cv;
                if (g0 >= 0) red_add_v2(&O[(long)g0 * N + col0], w0 * v00, w0 * v01);
                if (g1 >= 0) red_add_v2(&O[(long)g1 * N + col0], w1 * v10, w1 * v11);
            }
        }
    }
}

// ---- fused expert megakernel: layer-1 blocks then layer-2 blocks (1 launch) --
__global__ __launch_bounds__(256, 2)
void expert_kernel(const __half* __restrict__ xh,
                   const __half* __restrict__ W1h, const float* __restrict__ b1,
                   __half* __restrict__ h,
                   const __half* __restrict__ W2h, const float* __restrict__ b2,
                   float* __restrict__ out,
                   const int* __restrict__ perm,
                   const int* __restrict__ tile_expert,
                   const float* __restrict__ wslot,
                   int* __restrict__ done1)
{
    extern __shared__ __half smem[];
    const int bid = blockIdx.x;

    if (bid < G1_BLOCKS) {
        // ---- layer 1: h = fp16(GELU(xh[perm] @ W1h[e] + b1[e]))
        const int mtile = bid / G1_NT;
        const int ntile = bid - mtile * G1_NT;
        const int e = tile_expert[mtile];
        if (e < 0) return;
        gemm_body<true, 1, true>(mtile, ntile,
                                 xh,
                                 W1h + (long)e * D_DIM * H_DIM,
                                 b1 + (long)e * H_DIM,
                                 h, H_DIM, D_DIM,
                                 perm, nullptr, smem);
        __syncthreads();
        if (threadIdx.x == 0) {
            __threadfence();
            atomicAdd(&done1[mtile], 1);
        }
    } else {
        // ---- layer 2 (waits for its mtile's layer-1 tiles):
        //      out[token] += wslot[slot] * (h[slot] @ W2h[e] + b2[e])
        const int b2i   = bid - G1_BLOCKS;
        const int mtile = b2i / G2_NT;
        const int ntile = b2i - mtile * G2_NT;
        const int e = tile_expert[mtile];
        if (e < 0) return;
        if (threadIdx.x == 0) {
            volatile int* c = &done1[mtile];
            while (*c < G1_NT) __nanosleep(64);
            __threadfence();
        }
        __syncthreads();
        gemm_body<false, 2, false>(mtile, ntile,
                                   h,
                                   W2h + (long)e * H_DIM * D_DIM,
                                   b2 + (long)e * D_DIM,
                                   out, D_DIM, H_DIM,
                                   perm, wslot, smem);
    }
}

// ---------------- router GEMM: fp16 hi/lo split + fused W1/W2 converters ----
constexpr int RAS = 40;
constexpr int RBS = 136;
constexpr int RA_HELE = BM * RAS;
constexpr int RB_HELE = BK * RBS;
constexpr int SPLIT_SMEM_BYTES = (4 * RA_HELE + 4 * RB_HELE) * 2;
constexpr int SPLIT_YT = T_TOK / BM;            // 64 real m-tiles
constexpr int CONV_Y   = 24;                    // extra block rows for W conversion
constexpr long CONV_THREADS = (long)CONV_Y * 8 * 256;   // 49152

__global__ __launch_bounds__(256, 2)
void gemm_split_f16_kernel(const __half* __restrict__ Ahi, const __half* __restrict__ Alo,
                           const __half* __restrict__ Bhi, const __half* __restrict__ Blo,
                           const float* __restrict__ bias,
                           float* __restrict__ C, int N, int Kdim,
                           const float4* __restrict__ W1, const float4* __restrict__ W2,
                           __half* __restrict__ W1h, __half* __restrict__ W2h)
{
    const int mtile = blockIdx.y;
    if (mtile >= SPLIT_YT) {
        long cb = (long)(mtile - SPLIT_YT) * gridDim.x + blockIdx.x;
        const long total = (W1E + W2E) / 4;
        for (long i = cb * 256 + threadIdx.x; i < total; i += CONV_THREADS) {
            if (i < W1E / 4) {
                float4 v = W1[i];
                __half2* p = reinterpret_cast<__half2*>(W1h + i * 4);
                p[0] = __floats2half2_rn(v.x, v.y);
                p[1] = __floats2half2_rn(v.z, v.w);
            } else {
                long j = i - W1E / 4;
                float4 v = W2[j];
                __half2* p = reinterpret_cast<__half2*>(W2h + j * 4);
                p[0] = __floats2half2_rn(v.x, v.y);
                p[1] = __floats2half2_rn(v.z, v.w);
            }
        }
        return;
    }

    extern __shared__ __half hsmem[];
    __half* AsH = hsmem;
    __half* AsL = AsH + 2 * RA_HELE;
    __half* BsH = AsL + 2 * RA_HELE;
    __half* BsL = BsH + 2 * RB_HELE;

    const int ntile = blockIdx.x;
    const int tid   = threadIdx.x;
    const int lane  = tid & 31;
    const int warp  = tid >> 5;
    const int warpM = warp & 1;
    const int warpN = warp >> 1;
    const int mbase = mtile * BM;
    const int nbase = ntile * BN;

    float acc[4][4][4];
    #pragma unroll
    for (int mi = 0; mi < 4; mi++)
        #pragma unroll
        for (int ni = 0; ni < 4; ni++)
            #pragma unroll
            for (int r = 0; r < 4; r++) acc[mi][ni][r] = 0.0f;

    const int KT = Kdim / BK;

    auto load_tiles = [&](int kt, int stage) {
        const int k0 = kt * BK;
        #pragma unroll
        for (int i = 0; i < 2; i++) {
            int c   = tid + i * 256;
            int r   = c >> 2;
            int off = (c & 3) * 8;
            long go = (long)(mbase + r) * Kdim + k0 + off;
            cp_async16(&AsH[stage * RA_HELE + r * RAS + off], Ahi + go, 16);
            cp_async16(&AsL[stage * RA_HELE + r * RAS + off], Alo + go, 16);
        }
        #pragma unroll
        for (int i = 0; i < 2; i++) {
            int c   = tid + i * 256;
            int r   = c >> 4;
            int off = (c & 15) * 8;
            long go = (long)(k0 + r) * N + nbase + off;
            cp_async16(&BsH[stage * RB_HELE + r * RBS + off], Bhi + go, 16);
            cp_async16(&BsL[stage * RB_HELE + r * RBS + off], Blo + go, 16);
        }
        asm volatile("cp.async.commit_group;\n" ::: "memory");
    };

    const uint32_t ash_u = smem_u32(AsH);
    const uint32_t asl_u = smem_u32(AsL);
    const uint32_t bsh_u = smem_u32(BsH);
    const uint32_t bsl_u = smem_u32(BsL);
    const int tl = lane >> 3;
    const int lr = lane & 7;
    const int a_row0 = warpM * 64 + (tl & 1) * 8 + lr;
    const int a_col0 = (tl >> 1) * 8;
    const int b_krow0 = (tl & 1) * 8 + lr;
    const int b_col0  = warpN * 32 + (tl >> 1) * 8;

    load_tiles(0, 0);
    for (int kt = 0; kt < KT; kt++) {
        if (kt + 1 < KT) {
            load_tiles(kt + 1, (kt + 1) & 1);
            asm volatile("cp.async.wait_group 1;\n" ::: "memory");
        } else {
            asm volatile("cp.async.wait_group 0;\n" ::: "memory");
        }
        __syncthreads();

        const uint32_t ashu = ash_u + (kt & 1) * (RA_HELE * 2);
        const uint32_t aslu = asl_u + (kt & 1) * (RA_HELE * 2);
        const uint32_t bshu = bsh_u + (kt & 1) * (RB_HELE * 2);
        const uint32_t bslu = bsl_u + (kt & 1) * (RB_HELE * 2);

        #pragma unroll
        for (int ks = 0; ks < 2; ks++) {
            uint32_t ah[4][4], al[4][4];
            #pragma unroll
            for (int mi = 0; mi < 4; mi++) {
                uint32_t off = ((a_row0 + mi * 16) * RAS + ks * 16 + a_col0) * 2;
                ldsm_x4(ah[mi][0], ah[mi][1], ah[mi][2], ah[mi][3], ashu + off);
                ldsm_x4(al[mi][0], al[mi][1], al[mi][2], al[mi][3], aslu + off);
            }
            uint32_t bh[4][2], bl[4][2];
            #pragma unroll
            for (int nj = 0; nj < 2; nj++) {
                uint32_t off = ((b_krow0 + ks * 16) * RBS + b_col0 + nj * 16) * 2;
                ldsm_x4_t(bh[2 * nj][0], bh[2 * nj][1], bh[2 * nj + 1][0], bh[2 * nj + 1][1], bshu + off);
                ldsm_x4_t(bl[2 * nj][0], bl[2 * nj][1], bl[2 * nj + 1][0], bl[2 * nj + 1][1], bslu + off);
            }
            #pragma unroll
            for (int mi = 0; mi < 4; mi++)
                #pragma unroll
                for (int ni = 0; ni < 4; ni++) {
                    mma_f16(acc[mi][ni], ah[mi][0], ah[mi][1], ah[mi][2], ah[mi][3],
                            bl[ni][0], bl[ni][1]);
                    mma_f16(acc[mi][ni], al[mi][0], al[mi][1], al[mi][2], al[mi][3],
                            bh[ni][0], bh[ni][1]);
                    mma_f16(acc[mi][ni], ah[mi][0], ah[mi][1], ah[mi][2], ah[mi][3],
                            bh[ni][0], bh[ni][1]);
                }
        }
        __syncthreads();
    }

    #pragma unroll
    for (int mi = 0; mi < 4; mi++) {
        #pragma unroll
        for (int ni = 0; ni < 4; ni++) {
            int row0 = mbase + warpM * 64 + mi * 16 + (lane >> 2);
            int col0 = nbase + warpN * 32 + ni * 8 + (lane & 3) * 2;
            float bv0 = bias[col0], bv1 = bias[col0 + 1];
            float v00 = gelu_exact(acc[mi][ni][0] + bv0);
            float v01 = gelu_exact(acc[mi][ni][1] + bv1);
            float v10 = gelu_exact(acc[mi][ni][2] + bv0);
            float v11 = gelu_exact(acc[mi][ni][3] + bv1);
            *reinterpret_cast<float2*>(&C[(long)(row0    ) * N + col0]) = make_float2(v00, v01);
            *reinterpret_cast<float2*>(&C[(long)(row0 + 8) * N + col0]) = make_float2(v10, v11);
        }
    }
}

// ---------------- prep: init + x/Wr1 fp16 splits + zero out/done1 -----------
__global__ void prep_kernel(const float4* __restrict__ x, const float4* __restrict__ Wr1,
                            __half* __restrict__ xh, __half* __restrict__ xl,
                            __half* __restrict__ wh, __half* __restrict__ wl,
                            int* __restrict__ perm, int* __restrict__ counts,
                            int* __restrict__ done, int* __restrict__ done1,
                            float4* __restrict__ out4)
{
    long i = (long)blockIdx.x * 256 + threadIdx.x;
    if (i < MPAD)   perm[i] = -1;
    if (i < E_EXP)  counts[i] = 0;
    if (i == 0)     *done = 0;
    if (i < MTILES) done1[i] = 0;
    if (i < OUT4)   out4[i] = make_float4(0.0f, 0.0f, 0.0f, 0.0f);

    if (i < XE / 4) {
        float4 v = x[i];
        __half h0 = __float2half_rn(v.x), h1 = __float2half_rn(v.y);
        __half h2 = __float2half_rn(v.z), h3 = __float2half_rn(v.w);
        __half2* ph = reinterpret_cast<__half2*>(xh + i * 4);
        ph[0] = __halves2half2(h0, h1);
        ph[1] = __halves2half2(h2, h3);
        __half2* pl = reinterpret_cast<__half2*>(xl + i * 4);
        pl[0] = __floats2half2_rn(v.x - __half2float(h0), v.y - __half2float(h1));
        pl[1] = __floats2half2_rn(v.z - __half2float(h2), v.w - __half2float(h3));
    } else if (i < (XE + WR1E) / 4) {
        long j = i - XE / 4;
        float4 v = Wr1[j];
        __half h0 = __float2half_rn(v.x), h1 = __float2half_rn(v.y);
        __half h2 = __float2half_rn(v.z), h3 = __float2half_rn(v.w);
        __half2* ph = reinterpret_cast<__half2*>(wh + j * 4);
        ph[0] = __halves2half2(h0, h1);
        ph[1] = __halves2half2(h2, h3);
        __half2* pl = reinterpret_cast<__half2*>(wl + j * 4);
        pl[0] = __floats2half2_rn(v.x - __half2float(h0), v.y - __half2float(h1));
        pl[1] = __floats2half2_rn(v.z - __half2float(h2), v.w - __half2float(h3));
    }
}

// ---------------- route: logits + softmax + top-2 + (last block) scan/fill --
__global__ void route_kernel(const float* __restrict__ H1,
                             const float* __restrict__ Wr2,
                             const float* __restrict__ br2,
                             int*   __restrict__ topk_idx,
                             float* __restrict__ topk_w,
                             int*   __restrict__ counts,
                             int*   __restrict__ done,
                             int*   __restrict__ perm,
                             int*   __restrict__ slot,
                             float* __restrict__ wslot,
                             int*   __restrict__ tile_expert)
{
    int warp = threadIdx.x >> 5, lane = threadIdx.x & 31;
    int t = blockIdx.x * 8 + warp;
    const float* h = H1 + (long)t * D_DIM;

    float acc[E_EXP];
    #pragma unroll
    for (int e = 0; e < E_EXP; e++) acc[e] = 0.0f;

    #pragma unroll 4
    for (int i = 0; i < D_DIM / 32; i++) {
        int d = i * 32 + lane;
        float hv = h[d];
        const float4* w4 = reinterpret_cast<const float4*>(Wr2 + (long)d * E_EXP);
        float4 wa = w4[0], wb = w4[1];
        acc[0] += hv * wa.x; acc[1] += hv * wa.y; acc[2] += hv * wa.z; acc[3] += hv * wa.w;
        acc[4] += hv * wb.x; acc[5] += hv * wb.y; acc[6] += hv * wb.z; acc[7] += hv * wb.w;
    }
    #pragma unroll
    for (int e = 0; e < E_EXP; e++)
        #pragma unroll
        for (int off = 16; off; off >>= 1)
            acc[e] += __shfl_xor_sync(0xFFFFFFFFu, acc[e], off);

    if (lane == 0) {
        float l[E_EXP];
        #pragma unroll
        for (int e = 0; e < E_EXP; e++) l[e] = acc[e] + br2[e];
        int e0 = 0;
        #pragma unroll
        for (int e = 1; e < E_EXP; e++) if (l[e] > l[e0]) e0 = e;
        int e1 = -1;
        #pragma unroll
        for (int e = 0; e < E_EXP; e++)
            if (e != e0 && (e1 < 0 || l[e] > l[e1])) e1 = e;
        float m  = l[e0];
        float p0 = expf(l[e0] - m);
        float p1 = expf(l[e1] - m);
        float inv = 1.0f / (p0 + p1);
        topk_idx[t * 2]     = e0;
        topk_idx[t * 2 + 1] = e1;
        topk_w[t * 2]       = p0 * inv;
        topk_w[t * 2 + 1]   = p1 * inv;
        atomicAdd(&counts[e0], 1);
        atomicAdd(&counts[e1], 1);
    }

    __syncthreads();
    __shared__ int is_last;
    if (threadIdx.x == 0) {
        __threadfence();
        int prev = atomicAdd(done, 1);
        is_last = (prev == (int)gridDim.x - 1);
    }
    __syncthreads();
    if (!is_last) return;
    __threadfence();

    __shared__ int s_off[E_EXP + 1];
    __shared__ int s_fill[E_EXP];
    if (threadIdx.x == 0) {
        int off = 0;
        for (int e = 0; e < E_EXP; e++) {
            s_off[e] = off;
            off += (counts[e] + 127) & ~127;
        }
        s_off[E_EXP] = off;
        int e = 0;
        for (int tile = 0; tile < MTILES; tile++) {
            int r = tile * 128;
            if (r >= off) { tile_expert[tile] = -1; continue; }
            while (e < E_EXP && r >= s_off[e + 1]) e++;
            tile_expert[tile] = e;
        }
    }
    if (threadIdx.x < E_EXP) s_fill[threadIdx.x] = 0;
    __syncthreads();

    for (int tt = threadIdx.x; tt < T_TOK; tt += 256) {
        #pragma unroll
        for (int k = 0; k < 2; k++) {
            int e   = topk_idx[tt * 2 + k];
            int pos = s_off[e] + atomicAdd(&s_fill[e], 1);
            perm[pos]        = tt;
            slot[tt * 2 + k] = pos;
            wslot[pos]       = topk_w[tt * 2 + k];
        }
    }
}

// ---------------- launch ----------------
extern "C" void kernel_launch(void* const* d_in, const int* in_sizes, int n_in,
                              void* d_out, int out_size)
{
    const float* x   = (const float*)d_in[0];
    const float* Wr1 = (const float*)d_in[1];
    const float* br1 = (const float*)d_in[2];
    const float* Wr2 = (const float*)d_in[3];
    const float* br2 = (const float*)d_in[4];
    const float* W1  = (const float*)d_in[5];
    const float* b1  = (const float*)d_in[6];
    const float* W2  = (const float*)d_in[7];
    const float* b2  = (const float*)d_in[8];
    float* out = (float*)d_out;

    void *pH1, *ph, *pW1h, *pW2h, *pxh, *pxl, *pwh, *pwl;
    void *pti, *ptw, *pws, *pc, *pp, *ps, *pte, *pd, *pd1;
    cudaGetSymbolAddress(&pH1,  g_H1);
    cudaGetSymbolAddress(&ph,   g_h);
    cudaGetSymbolAddress(&pW1h, g_W1h);
    cudaGetSymbolAddress(&pW2h, g_W2h);
    cudaGetSymbolAddress(&pxh,  g_xh);
    cudaGetSymbolAddress(&pxl,  g_xl);
    cudaGetSymbolAddress(&pwh,  g_wh);
    cudaGetSymbolAddress(&pwl,  g_wl);
    cudaGetSymbolAddress(&pti,  g_topk_idx);
    cudaGetSymbolAddress(&ptw,  g_topk_w);
    cudaGetSymbolAddress(&pws,  g_wslot);
    cudaGetSymbolAddress(&pc,   g_counts);
    cudaGetSymbolAddress(&pp,   g_perm);
    cudaGetSymbolAddress(&ps,   g_slot);
    cudaGetSymbolAddress(&pte,  g_tile_expert);
    cudaGetSymbolAddress(&pd,   g_done);
    cudaGetSymbolAddress(&pd1,  g_done1);

    cudaFuncSetAttribute(gemm_split_f16_kernel,
                         cudaFuncAttributeMaxDynamicSharedMemorySize, SPLIT_SMEM_BYTES);
    cudaFuncSetAttribute(expert_kernel,
                         cudaFuncAttributeMaxDynamicSharedMemorySize, GEMM_SMEM_BYTES);

    // 0) prep: init + x/Wr1 fp16 splits + zero out/done1 (no separate memset)
    long nprep4 = (XE + WR1E) / 4;
    prep_kernel<<<(unsigned)((nprep4 + 255) / 256), 256>>>(
        (const float4*)x, (const float4*)Wr1,
        (__half*)pxh, (__half*)pxl, (__half*)pwh, (__half*)pwl,
        (int*)pp, (int*)pc, (int*)pd, (int*)pd1, (float4*)out);

    // 1) router hidden: H1 = GELU(x @ Wr1 + br1), fp16 split (near-fp32),
    //    + fused converter blocks turning W1/W2 into fp16 in the scheduling tail
    gemm_split_f16_kernel<<<dim3(D_DIM / BN, SPLIT_YT + CONV_Y), 256, SPLIT_SMEM_BYTES>>>(
        (const __half*)pxh, (const __half*)pxl, (const __half*)pwh, (const __half*)pwl,
        br1, (float*)pH1, D_DIM, D_DIM,
        (const float4*)W1, (const float4*)W2, (__half*)pW1h, (__half*)pW2h);

    // 2) logits + softmax + top-2 + counts + scan + fill (+ per-slot weights)
    route_kernel<<<T_TOK / 8, 256>>>((const float*)pH1, Wr2, br2,
                                     (int*)pti, (float*)ptw, (int*)pc, (int*)pd,
                                     (int*)pp, (int*)ps, (float*)pws, (int*)pte);

    // 3) fused expert megakernel: layer-1 tiles + dependency-gated layer-2 tiles
    expert_kernel<<<G1_BLOCKS + G2_BLOCKS, 256, GEMM_SMEM_BYTES>>>(
        (const __half*)pxh, (const __half*)pW1h, b1, (__half*)ph,
        (const __half*)pW2h, b2, out,
        (const int*)pp, (const int*)pte, (const float*)pws, (int*)pd1);
}